// round 7
// baseline (speedup 1.0000x reference)
#include <cuda_runtime.h>
#include <cstdint>

// Problem constants
#define Bv   8
#define Sv   1024
#define Dv   768
#define Hv   12
#define DHv  64
#define MLPv 3072
#define ROWS (Bv*Sv)            // 8192

// GEMM tiling
#define BK       32
#define LDK      36                     // 32 + 4 pad (conflict-free fragment LDS)
#define STAGE_FLTS (128*LDK)            // floats per operand per stage
#define SMEM_FLTS  (6*STAGE_FLTS)       // 3 stages x (A,B) = 110592 B
#define SMEMSZ     (SMEM_FLTS*4)

// ---------------- scratch (static device memory; no allocs) ----------------
__device__ float g_xn [ROWS*Dv];
__device__ float g_q  [ROWS*Dv];
__device__ float g_k  [ROWS*Dv];
__device__ float g_v  [ROWS*Dv];
__device__ float g_ctx[ROWS*Dv];
__device__ float g_x2 [ROWS*Dv];
__device__ float g_xn2[ROWS*Dv];
__device__ float g_h1 [ROWS*MLPv];
__device__ float g_wqT[Dv*Dv];
__device__ float g_wkT[Dv*Dv];
__device__ float g_wvT[Dv*Dv];
__device__ float g_woT[Dv*Dv];
__device__ float g_w1T[MLPv*Dv];   // [3072, 768]
__device__ float g_w2T[Dv*MLPv];   // [768, 3072]

// ---------------- helpers ----------------------------------------------------
__device__ __forceinline__ uint32_t smem_u32(const void* p) {
    uint32_t a;
    asm("{ .reg .u64 t; cvta.to.shared.u64 t, %1; cvt.u32.u64 %0, t; }" : "=r"(a) : "l"(p));
    return a;
}
__device__ __forceinline__ float rtf32(float x) {   // round-to-nearest tf32
    uint32_t u; asm("cvt.rna.tf32.f32 %0, %1;" : "=r"(u) : "f"(x));
    return __uint_as_float(u);
}

// ---------------- weight transpose + round to tf32 ---------------------------
// W [Kd, Nd] row-major  ->  WT [Nd, Kd]
__global__ __launch_bounds__(256)
void transpose_round(const float* __restrict__ W, float* __restrict__ WT, int Kd, int Nd) {
    __shared__ float t[32][33];
    int n0 = blockIdx.x * 32, k0 = blockIdx.y * 32;
    int tx = threadIdx.x & 31, ty = threadIdx.x >> 5;  // 32 x 8
    #pragma unroll
    for (int i = 0; i < 32; i += 8)
        t[ty + i][tx] = W[(size_t)(k0 + ty + i) * Nd + n0 + tx];
    __syncthreads();
    #pragma unroll
    for (int i = 0; i < 32; i += 8)
        WT[(size_t)(n0 + ty + i) * Kd + k0 + tx] = rtf32(t[tx][ty + i]);
}

// ---------------- LayerNorm (outputs rounded to tf32: GEMM-A operands) -------
__global__ __launch_bounds__(256)
void ln_kernel(const float* __restrict__ x, const float* __restrict__ g,
               const float* __restrict__ b, float* __restrict__ y) {
    int row = blockIdx.x;
    int t = threadIdx.x;
    const float* xr = x + (size_t)row * Dv;
    float v0 = xr[t], v1 = xr[t + 256], v2 = xr[t + 512];
    float s  = v0 + v1 + v2;
    float s2 = v0*v0 + v1*v1 + v2*v2;
    #pragma unroll
    for (int o = 16; o; o >>= 1) {
        s  += __shfl_xor_sync(0xFFFFFFFFu, s,  o);
        s2 += __shfl_xor_sync(0xFFFFFFFFu, s2, o);
    }
    __shared__ float rs[8], rs2[8];
    int w = t >> 5, lane = t & 31;
    if (lane == 0) { rs[w] = s; rs2[w] = s2; }
    __syncthreads();
    float tot = 0.f, tot2 = 0.f;
    #pragma unroll
    for (int i = 0; i < 8; i++) { tot += rs[i]; tot2 += rs2[i]; }
    float mu  = tot * (1.0f / Dv);
    float var = tot2 * (1.0f / Dv) - mu * mu;
    float inv = rsqrtf(var + 1e-6f);
    float* yr = y + (size_t)row * Dv;
    yr[t]       = rtf32((v0 - mu) * inv * g[t]       + b[t]);
    yr[t + 256] = rtf32((v1 - mu) * inv * g[t + 256] + b[t + 256]);
    yr[t + 512] = rtf32((v2 - mu) * inv * g[t + 512] + b[t + 512]);
}

// ---------------- tf32 tensor-core GEMM: C[M,N] = A[M,K] @ B[N,K]^T ----------
// mma.sync.aligned.m16n8k8 (legacy warp-MMA; valid on plain compute_103)
// EPI: 1 = +bias +res ; 2 = +bias, relu, round-tf32 ; 3 = +bias, scatter [B,H,S,64]
// mremap != 0: grid.y covers only query rows < 512 of each batch (Q projection)
template<int EPI>
__global__ __launch_bounds__(256, 2)
void tgemm(const float* __restrict__ A, const float* __restrict__ Bw,
           const float* __restrict__ bias, const float* __restrict__ res,
           float* __restrict__ C, int M, int N, int K, int mremap) {
    extern __shared__ float smem[];
    float* sA = smem;                     // [3][128][LDK]
    float* sB = smem + 3 * STAGE_FLTS;
    const uint32_t saA = smem_u32(sA);
    const uint32_t saB = smem_u32(sB);

    const int tid = threadIdx.x;
    int by = blockIdx.y;
    if (mremap) by = (by >> 2) * 8 + (by & 3);
    const int rowBase = by * 128, colBase = blockIdx.x * 128;
    const int warp = tid >> 5, lane = tid & 31;
    const int wm = warp >> 2, wn = warp & 3;     // warps: 2 (m) x 4 (n)
    const int r = lane >> 2, c = lane & 3;

    auto load = [&](int j, int s) {
        int k0 = j * BK;
        #pragma unroll
        for (int e = 0; e < 4; e++) {
            int idx = tid + 256 * e;             // 0..1023
            int row = idx >> 3, kc = (idx & 7) * 4;
            const float* ga = A  + (size_t)(rowBase + row) * K + k0 + kc;
            const float* gb = Bw + (size_t)(colBase + row) * K + k0 + kc;
            uint32_t da = saA + (uint32_t)(s * STAGE_FLTS + row * LDK + kc) * 4;
            uint32_t db = saB + (uint32_t)(s * STAGE_FLTS + row * LDK + kc) * 4;
            asm volatile("cp.async.cg.shared.global [%0], [%1], 16;" :: "r"(da), "l"(ga));
            asm volatile("cp.async.cg.shared.global [%0], [%1], 16;" :: "r"(db), "l"(gb));
        }
        asm volatile("cp.async.commit_group;" ::: "memory");
    };

    float acc[4][4][4];
    #pragma unroll
    for (int mt = 0; mt < 4; mt++)
        #pragma unroll
        for (int nt = 0; nt < 4; nt++)
            #pragma unroll
            for (int i = 0; i < 4; i++) acc[mt][nt][i] = 0.f;

    load(0, 0);
    load(1, 1);

    const int nch = K / BK;
    for (int i = 0; i < nch; i++) {
        if (i + 2 < nch) load(i + 2, (i + 2) % 3);
        else asm volatile("cp.async.commit_group;" ::: "memory");
        asm volatile("cp.async.wait_group 2;" ::: "memory");
        __syncthreads();

        const uint32_t* pA = (const uint32_t*)(sA + (i % 3) * STAGE_FLTS);
        const uint32_t* pB = (const uint32_t*)(sB + (i % 3) * STAGE_FLTS);

        #pragma unroll
        for (int ks = 0; ks < 4; ks++) {
            uint32_t af[4][4], bf[4][2];
            #pragma unroll
            for (int mt = 0; mt < 4; mt++) {
                const uint32_t* p = pA + (wm * 64 + mt * 16 + r) * LDK + ks * 8 + c;
                af[mt][0] = p[0];
                af[mt][1] = p[8 * LDK];
                af[mt][2] = p[4];
                af[mt][3] = p[8 * LDK + 4];
            }
            #pragma unroll
            for (int nt = 0; nt < 4; nt++) {
                const uint32_t* p = pB + (wn * 32 + nt * 8 + r) * LDK + ks * 8 + c;
                bf[nt][0] = p[0];
                bf[nt][1] = p[4];
            }
            #pragma unroll
            for (int mt = 0; mt < 4; mt++)
                #pragma unroll
                for (int nt = 0; nt < 4; nt++)
                    asm volatile(
                        "mma.sync.aligned.m16n8k8.row.col.f32.tf32.tf32.f32 "
                        "{%0,%1,%2,%3}, {%4,%5,%6,%7}, {%8,%9}, {%0,%1,%2,%3};"
                        : "+f"(acc[mt][nt][0]), "+f"(acc[mt][nt][1]),
                          "+f"(acc[mt][nt][2]), "+f"(acc[mt][nt][3])
                        : "r"(af[mt][0]), "r"(af[mt][1]), "r"(af[mt][2]), "r"(af[mt][3]),
                          "r"(bf[nt][0]), "r"(bf[nt][1]));
        }
        __syncthreads();
    }

    // Epilogue: regs -> smem tile -> coalesced global stores
    float* tile = smem;                   // [128][132]
    #pragma unroll
    for (int mt = 0; mt < 4; mt++)
        #pragma unroll
        for (int nt = 0; nt < 4; nt++) {
            int r0 = wm * 64 + mt * 16 + r;
            int c0 = wn * 32 + nt * 8 + 2 * c;
            tile[r0 * 132 + c0]           = acc[mt][nt][0];
            tile[r0 * 132 + c0 + 1]       = acc[mt][nt][1];
            tile[(r0 + 8) * 132 + c0]     = acc[mt][nt][2];
            tile[(r0 + 8) * 132 + c0 + 1] = acc[mt][nt][3];
        }
    __syncthreads();

    float4 b4 = *(const float4*)(bias + colBase + lane * 4);
    int col0 = colBase + lane * 4;
    int hh = col0 >> 6, dd = col0 & 63;          // for EPI==3
    #pragma unroll
    for (int rr = 0; rr < 16; rr++) {
        int trow = warp * 16 + rr;
        int row  = rowBase + trow;
        float4 v = *(float4*)&tile[trow * 132 + lane * 4];
        v.x += b4.x; v.y += b4.y; v.z += b4.z; v.w += b4.w;
        if (EPI == 1) {
            float4 r4 = *(const float4*)(res + (size_t)row * N + col0);
            v.x += r4.x; v.y += r4.y; v.z += r4.z; v.w += r4.w;
        }
        if (EPI == 2) {
            v.x = rtf32(fmaxf(v.x, 0.f)); v.y = rtf32(fmaxf(v.y, 0.f));
            v.z = rtf32(fmaxf(v.z, 0.f)); v.w = rtf32(fmaxf(v.w, 0.f));
        }
        if (EPI == 3) {
            int bb = row >> 10, ss = row & 1023;
            *(float4*)&C[(((size_t)(bb * Hv + hh) * Sv + ss) * DHv) + dd] = v;
        } else {
            *(float4*)&C[(size_t)row * N + col0] = v;
        }
    }
}

// ---------------- Attention (query rows < 512), flash-style fp32 ------------
__global__ __launch_bounds__(256)
void attn_kernel(const float* __restrict__ Q, const float* __restrict__ Kg,
                 const float* __restrict__ Vg, float* __restrict__ ctx) {
    __shared__ float Qs[64][64];
    __shared__ float Ks[32][65];
    __shared__ float Vs[32][65];
    const int b = blockIdx.z, h = blockIdx.y;
    const int bh = b * Hv + h;
    const int qbase = blockIdx.x * 64;
    const int tid = threadIdx.x;
    const int warp = tid >> 5, lane = tid & 31;

    const float* Qbh = Q + ((size_t)bh * Sv + qbase) * DHv;
    #pragma unroll
    for (int e = 0; e < 4; e++) {
        int lin = tid + e * 256;
        int r = lin >> 4, c4 = (lin & 15) * 4;
        *(float4*)&Qs[r][c4] = *(const float4*)(Qbh + r * DHv + c4);
    }

    float m[8], l[8], acc0[8], acc1[8];
    #pragma unroll
    for (int r = 0; r < 8; r++) { m[r] = -1e30f; l[r] = 0.f; acc0[r] = 0.f; acc1[r] = 0.f; }

    const float* Kbh = Kg + (size_t)bh * Sv * DHv;
    const float* Vbh = Vg + (size_t)bh * Sv * DHv;

    for (int kt = 0; kt < Sv; kt += 32) {
        __syncthreads();
        #pragma unroll
        for (int e = 0; e < 8; e++) {
            int lin = tid + e * 256;
            int r = lin >> 6, c = lin & 63;
            Ks[r][c] = Kbh[(kt + r) * DHv + c];
            Vs[r][c] = Vbh[(kt + r) * DHv + c];
        }
        __syncthreads();

        float s[8];
        #pragma unroll
        for (int r = 0; r < 8; r++) s[r] = 0.f;
        #pragma unroll
        for (int i = 0; i < 64; i++) {
            float kv = Ks[lane][i];
            #pragma unroll
            for (int r = 0; r < 8; r++)
                s[r] = fmaf(Qs[warp * 8 + r][i], kv, s[r]);
        }

        #pragma unroll
        for (int r = 0; r < 8; r++) {
            float sv = s[r] * 0.125f;
            float smax = sv;
            #pragma unroll
            for (int o = 16; o; o >>= 1)
                smax = fmaxf(smax, __shfl_xor_sync(0xFFFFFFFFu, smax, o));
            float mnew = fmaxf(m[r], smax);
            float p = __expf(sv - mnew);
            float corr = __expf(m[r] - mnew);
            float psum = p;
            #pragma unroll
            for (int o = 16; o; o >>= 1)
                psum += __shfl_xor_sync(0xFFFFFFFFu, psum, o);
            l[r] = l[r] * corr + psum;
            acc0[r] *= corr; acc1[r] *= corr;
            #pragma unroll
            for (int k0 = 0; k0 < 32; k0++) {
                float pk = __shfl_sync(0xFFFFFFFFu, p, k0);
                acc0[r] = fmaf(pk, Vs[k0][lane],      acc0[r]);
                acc1[r] = fmaf(pk, Vs[k0][lane + 32], acc1[r]);
            }
            m[r] = mnew;
        }
    }

    #pragma unroll
    for (int r = 0; r < 8; r++) {
        int qr = qbase + warp * 8 + r;
        float invl = 1.0f / l[r];
        size_t base = ((size_t)b * Sv + qr) * Dv + h * DHv;
        ctx[base + lane]      = rtf32(acc0[r] * invl);
        ctx[base + lane + 32] = rtf32(acc1[r] * invl);
    }
}

// ---------------- Masked rows (>=512): ctx = mean_k v -----------------------
__global__ __launch_bounds__(256)
void meanv_kernel(const float* __restrict__ Vg, float* __restrict__ ctx) {
    const int h = blockIdx.x, b = blockIdx.y;
    const int bh = b * Hv + h;
    const int tid = threadIdx.x;
    const int d = tid & 63, slice = tid >> 6;
    const float* Vbh = Vg + (size_t)bh * Sv * DHv;
    float s = 0.f;
    for (int k = slice * 256; k < slice * 256 + 256; k++)
        s += Vbh[k * DHv + d];
    __shared__ float red[4][64];
    __shared__ float mv[64];
    red[slice][d] = s;
    __syncthreads();
    if (tid < 64)
        mv[tid] = rtf32((red[0][tid] + red[1][tid] + red[2][tid] + red[3][tid]) * (1.0f / Sv));
    __syncthreads();
    float val = mv[d];
    for (int r = slice; r < 512; r += 4)
        ctx[((size_t)b * Sv + 512 + r) * Dv + h * DHv + d] = val;
}

// ---------------- driver -----------------------------------------------------
extern "C" void kernel_launch(void* const* d_in, const int* in_sizes, int n_in,
                              void* d_out, int out_size) {
    const float* x    = (const float*)d_in[0];
    const float* Wq   = (const float*)d_in[1];
    const float* bq   = (const float*)d_in[2];
    const float* Wk   = (const float*)d_in[3];
    const float* bk   = (const float*)d_in[4];
    const float* Wv   = (const float*)d_in[5];
    const float* bv   = (const float*)d_in[6];
    const float* Wo   = (const float*)d_in[7];
    const float* bo   = (const float*)d_in[8];
    const float* ln1g = (const float*)d_in[9];
    const float* ln1b = (const float*)d_in[10];
    const float* ln2g = (const float*)d_in[11];
    const float* ln2b = (const float*)d_in[12];
    const float* W1   = (const float*)d_in[13];
    const float* b1   = (const float*)d_in[14];
    const float* W2   = (const float*)d_in[15];
    const float* b2   = (const float*)d_in[16];
    float* out = (float*)d_out;

    float *xn, *q, *k, *v, *ctx, *x2, *xn2, *h1;
    float *wqT, *wkT, *wvT, *woT, *w1T, *w2T;
    cudaGetSymbolAddress((void**)&xn,  g_xn);
    cudaGetSymbolAddress((void**)&q,   g_q);
    cudaGetSymbolAddress((void**)&k,   g_k);
    cudaGetSymbolAddress((void**)&v,   g_v);
    cudaGetSymbolAddress((void**)&ctx, g_ctx);
    cudaGetSymbolAddress((void**)&x2,  g_x2);
    cudaGetSymbolAddress((void**)&xn2, g_xn2);
    cudaGetSymbolAddress((void**)&h1,  g_h1);
    cudaGetSymbolAddress((void**)&wqT, g_wqT);
    cudaGetSymbolAddress((void**)&wkT, g_wkT);
    cudaGetSymbolAddress((void**)&wvT, g_wvT);
    cudaGetSymbolAddress((void**)&woT, g_woT);
    cudaGetSymbolAddress((void**)&w1T, g_w1T);
    cudaGetSymbolAddress((void**)&w2T, g_w2T);

    cudaFuncSetAttribute(tgemm<1>, cudaFuncAttributeMaxDynamicSharedMemorySize, SMEMSZ);
    cudaFuncSetAttribute(tgemm<2>, cudaFuncAttributeMaxDynamicSharedMemorySize, SMEMSZ);
    cudaFuncSetAttribute(tgemm<3>, cudaFuncAttributeMaxDynamicSharedMemorySize, SMEMSZ);

    // Weight transposes (rounded to tf32)
    transpose_round<<<dim3(Dv/32,   Dv/32),   256>>>(Wq, wqT, Dv,   Dv);
    transpose_round<<<dim3(Dv/32,   Dv/32),   256>>>(Wk, wkT, Dv,   Dv);
    transpose_round<<<dim3(Dv/32,   Dv/32),   256>>>(Wv, wvT, Dv,   Dv);
    transpose_round<<<dim3(Dv/32,   Dv/32),   256>>>(Wo, woT, Dv,   Dv);
    transpose_round<<<dim3(MLPv/32, Dv/32),   256>>>(W1, w1T, Dv,   MLPv);
    transpose_round<<<dim3(Dv/32,   MLPv/32), 256>>>(W2, w2T, MLPv, Dv);

    // 1. LN1
    ln_kernel<<<ROWS, 256>>>(x, ln1g, ln1b, xn);

    // 2. QKV projections (tensor core, scatter into [B,H,S,64]).
    //    Q only needed for query rows < 512 of each batch -> half M with tile remap.
    dim3 gD(Dv/128, ROWS/128);             // (6, 64)
    dim3 gQ(Dv/128, ROWS/256);             // (6, 32) remapped
    tgemm<3><<<gQ, 256, SMEMSZ>>>(xn, wqT, bq, nullptr, q, ROWS, Dv, Dv, 1);
    tgemm<3><<<gD, 256, SMEMSZ>>>(xn, wkT, bk, nullptr, k, ROWS, Dv, Dv, 0);
    tgemm<3><<<gD, 256, SMEMSZ>>>(xn, wvT, bv, nullptr, v, ROWS, Dv, Dv, 0);

    // 3. Attention
    attn_kernel<<<dim3(8, Hv, Bv), 256>>>(q, k, v, ctx);
    meanv_kernel<<<dim3(Hv, Bv), 256>>>(v, ctx);

    // 4. Output projection + residual
    tgemm<1><<<gD, 256, SMEMSZ>>>(ctx, woT, bo, x, x2, ROWS, Dv, Dv, 0);

    // 5. LN2
    ln_kernel<<<ROWS, 256>>>(x2, ln2g, ln2b, xn2);

    // 6. MLP
    dim3 gM(MLPv/128, ROWS/128);           // (24, 64)
    tgemm<2><<<gM, 256, SMEMSZ>>>(xn2, w1T, b1, nullptr, h1, ROWS, MLPv, Dv, 0);
    tgemm<1><<<gD, 256, SMEMSZ>>>(h1, w2T, b2, x2, out, ROWS, Dv, MLPv, 0);
}

// round 8
// speedup vs baseline: 1.4450x; 1.4450x over previous
#include <cuda_runtime.h>
#include <cstdint>

// Problem constants
#define Bv   8
#define Sv   1024
#define Dv   768
#define Hv   12
#define DHv  64
#define MLPv 3072
#define ROWS (Bv*Sv)            // 8192

// GEMM tiling
#define BK       32
#define LDK      36                     // 32 + 4 pad (conflict-free fragment LDS)
#define STAGE_FLTS (128*LDK)            // floats per operand per stage
#define SMEM_FLTS  (6*STAGE_FLTS)       // 3 stages x (A,B) = 110592 B
#define SMEMSZ     (SMEM_FLTS*4)

// Attention tiling
#define KVP  72                          // pad for Qs/Ks/Vs rows
#define PP   68                          // pad for P tile rows
#define ATTN_SMEM ((3*64*KVP + 64*PP + 256) * 4)   // 73728 B

// ---------------- scratch (static device memory; no allocs) ----------------
__device__ float g_xn [ROWS*Dv];
__device__ float g_q  [ROWS*Dv];
__device__ float g_k  [ROWS*Dv];
__device__ float g_v  [ROWS*Dv];
__device__ float g_ctx[ROWS*Dv];
__device__ float g_x2 [ROWS*Dv];
__device__ float g_xn2[ROWS*Dv];
__device__ float g_h1 [ROWS*MLPv];
__device__ float g_wqT[Dv*Dv];
__device__ float g_wkT[Dv*Dv];
__device__ float g_wvT[Dv*Dv];
__device__ float g_woT[Dv*Dv];
__device__ float g_w1T[MLPv*Dv];   // [3072, 768]
__device__ float g_w2T[Dv*MLPv];   // [768, 3072]

// ---------------- helpers ----------------------------------------------------
__device__ __forceinline__ uint32_t smem_u32(const void* p) {
    uint32_t a;
    asm("{ .reg .u64 t; cvta.to.shared.u64 t, %1; cvt.u32.u64 %0, t; }" : "=r"(a) : "l"(p));
    return a;
}
__device__ __forceinline__ float rtf32(float x) {   // round-to-nearest tf32
    uint32_t u; asm("cvt.rna.tf32.f32 %0, %1;" : "=r"(u) : "f"(x));
    return __uint_as_float(u);
}
__device__ __forceinline__ void mma_tf32_16x8x8(float* d, const uint32_t* a, const uint32_t* b) {
    asm volatile(
        "mma.sync.aligned.m16n8k8.row.col.f32.tf32.tf32.f32 "
        "{%0,%1,%2,%3}, {%4,%5,%6,%7}, {%8,%9}, {%0,%1,%2,%3};"
        : "+f"(d[0]), "+f"(d[1]), "+f"(d[2]), "+f"(d[3])
        : "r"(a[0]), "r"(a[1]), "r"(a[2]), "r"(a[3]), "r"(b[0]), "r"(b[1]));
}

// ---------------- weight transpose + round to tf32 ---------------------------
// W [Kd, Nd] row-major  ->  WT [Nd, Kd]
__global__ __launch_bounds__(256)
void transpose_round(const float* __restrict__ W, float* __restrict__ WT, int Kd, int Nd) {
    __shared__ float t[32][33];
    int n0 = blockIdx.x * 32, k0 = blockIdx.y * 32;
    int tx = threadIdx.x & 31, ty = threadIdx.x >> 5;  // 32 x 8
    #pragma unroll
    for (int i = 0; i < 32; i += 8)
        t[ty + i][tx] = W[(size_t)(k0 + ty + i) * Nd + n0 + tx];
    __syncthreads();
    #pragma unroll
    for (int i = 0; i < 32; i += 8)
        WT[(size_t)(n0 + ty + i) * Kd + k0 + tx] = rtf32(t[tx][ty + i]);
}

// ---------------- LayerNorm (outputs rounded to tf32: GEMM-A operands) -------
__global__ __launch_bounds__(256)
void ln_kernel(const float* __restrict__ x, const float* __restrict__ g,
               const float* __restrict__ b, float* __restrict__ y) {
    int row = blockIdx.x;
    int t = threadIdx.x;
    const float* xr = x + (size_t)row * Dv;
    float v0 = xr[t], v1 = xr[t + 256], v2 = xr[t + 512];
    float s  = v0 + v1 + v2;
    float s2 = v0*v0 + v1*v1 + v2*v2;
    #pragma unroll
    for (int o = 16; o; o >>= 1) {
        s  += __shfl_xor_sync(0xFFFFFFFFu, s,  o);
        s2 += __shfl_xor_sync(0xFFFFFFFFu, s2, o);
    }
    __shared__ float rs[8], rs2[8];
    int w = t >> 5, lane = t & 31;
    if (lane == 0) { rs[w] = s; rs2[w] = s2; }
    __syncthreads();
    float tot = 0.f, tot2 = 0.f;
    #pragma unroll
    for (int i = 0; i < 8; i++) { tot += rs[i]; tot2 += rs2[i]; }
    float mu  = tot * (1.0f / Dv);
    float var = tot2 * (1.0f / Dv) - mu * mu;
    float inv = rsqrtf(var + 1e-6f);
    float* yr = y + (size_t)row * Dv;
    yr[t]       = rtf32((v0 - mu) * inv * g[t]       + b[t]);
    yr[t + 256] = rtf32((v1 - mu) * inv * g[t + 256] + b[t + 256]);
    yr[t + 512] = rtf32((v2 - mu) * inv * g[t + 512] + b[t + 512]);
}

// ---------------- tf32 tensor-core GEMM: C[M,N] = A[M,K] @ B[N,K]^T ----------
// EPI: 1 = +bias +res ; 2 = +bias, relu, round-tf32 ; 3 = +bias, round-tf32, scatter [B,H,S,64]
template<int EPI>
__global__ __launch_bounds__(256, 2)
void tgemm(const float* __restrict__ A, const float* __restrict__ Bw,
           const float* __restrict__ bias, const float* __restrict__ res,
           float* __restrict__ C, int M, int N, int K, int mremap) {
    extern __shared__ float smem[];
    float* sA = smem;                     // [3][128][LDK]
    float* sB = smem + 3 * STAGE_FLTS;
    const uint32_t saA = smem_u32(sA);
    const uint32_t saB = smem_u32(sB);

    const int tid = threadIdx.x;
    int by = blockIdx.y;
    if (mremap) by = (by >> 2) * 8 + (by & 3);
    const int rowBase = by * 128, colBase = blockIdx.x * 128;
    const int warp = tid >> 5, lane = tid & 31;
    const int wm = warp >> 2, wn = warp & 3;     // warps: 2 (m) x 4 (n)
    const int r = lane >> 2, c = lane & 3;

    auto load = [&](int j, int s) {
        int k0 = j * BK;
        #pragma unroll
        for (int e = 0; e < 4; e++) {
            int idx = tid + 256 * e;             // 0..1023
            int row = idx >> 3, kc = (idx & 7) * 4;
            const float* ga = A  + (size_t)(rowBase + row) * K + k0 + kc;
            const float* gb = Bw + (size_t)(colBase + row) * K + k0 + kc;
            uint32_t da = saA + (uint32_t)(s * STAGE_FLTS + row * LDK + kc) * 4;
            uint32_t db = saB + (uint32_t)(s * STAGE_FLTS + row * LDK + kc) * 4;
            asm volatile("cp.async.cg.shared.global [%0], [%1], 16;" :: "r"(da), "l"(ga));
            asm volatile("cp.async.cg.shared.global [%0], [%1], 16;" :: "r"(db), "l"(gb));
        }
        asm volatile("cp.async.commit_group;" ::: "memory");
    };

    float acc[4][4][4];
    #pragma unroll
    for (int mt = 0; mt < 4; mt++)
        #pragma unroll
        for (int nt = 0; nt < 4; nt++)
            #pragma unroll
            for (int i = 0; i < 4; i++) acc[mt][nt][i] = 0.f;

    load(0, 0);
    load(1, 1);

    const int nch = K / BK;
    for (int i = 0; i < nch; i++) {
        if (i + 2 < nch) load(i + 2, (i + 2) % 3);
        else asm volatile("cp.async.commit_group;" ::: "memory");
        asm volatile("cp.async.wait_group 2;" ::: "memory");
        __syncthreads();

        const uint32_t* pA = (const uint32_t*)(sA + (i % 3) * STAGE_FLTS);
        const uint32_t* pB = (const uint32_t*)(sB + (i % 3) * STAGE_FLTS);

        #pragma unroll
        for (int ks = 0; ks < 4; ks++) {
            uint32_t af[4][4], bf[4][2];
            #pragma unroll
            for (int mt = 0; mt < 4; mt++) {
                const uint32_t* p = pA + (wm * 64 + mt * 16 + r) * LDK + ks * 8 + c;
                af[mt][0] = p[0];
                af[mt][1] = p[8 * LDK];
                af[mt][2] = p[4];
                af[mt][3] = p[8 * LDK + 4];
            }
            #pragma unroll
            for (int nt = 0; nt < 4; nt++) {
                const uint32_t* p = pB + (wn * 32 + nt * 8 + r) * LDK + ks * 8 + c;
                bf[nt][0] = p[0];
                bf[nt][1] = p[4];
            }
            #pragma unroll
            for (int mt = 0; mt < 4; mt++)
                #pragma unroll
                for (int nt = 0; nt < 4; nt++)
                    mma_tf32_16x8x8(acc[mt][nt], af[mt], bf[nt]);
        }
        __syncthreads();
    }

    // Epilogue: regs -> smem tile -> coalesced global stores
    float* tile = smem;                   // [128][132]
    #pragma unroll
    for (int mt = 0; mt < 4; mt++)
        #pragma unroll
        for (int nt = 0; nt < 4; nt++) {
            int r0 = wm * 64 + mt * 16 + r;
            int c0 = wn * 32 + nt * 8 + 2 * c;
            tile[r0 * 132 + c0]           = acc[mt][nt][0];
            tile[r0 * 132 + c0 + 1]       = acc[mt][nt][1];
            tile[(r0 + 8) * 132 + c0]     = acc[mt][nt][2];
            tile[(r0 + 8) * 132 + c0 + 1] = acc[mt][nt][3];
        }
    __syncthreads();

    float4 b4 = *(const float4*)(bias + colBase + lane * 4);
    int col0 = colBase + lane * 4;
    int hh = col0 >> 6, dd = col0 & 63;          // for EPI==3
    #pragma unroll
    for (int rr = 0; rr < 16; rr++) {
        int trow = warp * 16 + rr;
        int row  = rowBase + trow;
        float4 v = *(float4*)&tile[trow * 132 + lane * 4];
        v.x += b4.x; v.y += b4.y; v.z += b4.z; v.w += b4.w;
        if (EPI == 1) {
            float4 r4 = *(const float4*)(res + (size_t)row * N + col0);
            v.x += r4.x; v.y += r4.y; v.z += r4.z; v.w += r4.w;
        }
        if (EPI == 2) {
            v.x = rtf32(fmaxf(v.x, 0.f)); v.y = rtf32(fmaxf(v.y, 0.f));
            v.z = rtf32(fmaxf(v.z, 0.f)); v.w = rtf32(fmaxf(v.w, 0.f));
        }
        if (EPI == 3) {
            v.x = rtf32(v.x); v.y = rtf32(v.y); v.z = rtf32(v.z); v.w = rtf32(v.w);
            int bb = row >> 10, ss = row & 1023;
            *(float4*)&C[(((size_t)(bb * Hv + hh) * Sv + ss) * DHv) + dd] = v;
        } else {
            *(float4*)&C[(size_t)row * N + col0] = v;
        }
    }
}

// ---------------- Attention (query rows < 512) via tf32 MMA flash -----------
// grid (8 qtiles, H, B), 256 threads = 8 warps = 4(m) x 2(n)
__global__ __launch_bounds__(256, 2)
void attn_mma(const float* __restrict__ Q, const float* __restrict__ Kg,
              const float* __restrict__ Vg, float* __restrict__ ctx) {
    extern __shared__ float sm[];
    float* Qs   = sm;                     // [64][KVP]
    float* Ks   = Qs + 64 * KVP;          // [64][KVP]
    float* Vs   = Ks + 64 * KVP;          // [64][KVP]
    float* Ps   = Vs + 64 * KVP;          // [64][PP]
    float* redm = Ps + 64 * PP;           // [2][64]
    float* redl = redm + 128;             // [2][64]

    const int b = blockIdx.z, h = blockIdx.y;
    const int bh = b * Hv + h;
    const int qbase = blockIdx.x * 64;
    const int tid = threadIdx.x, warp = tid >> 5, lane = tid & 31;
    const int wm = warp >> 1, wn = warp & 1;
    const int r = lane >> 2, c = lane & 3;
    const int m0 = wm * 16;

    // Stage Q (pre-scaled by 1/sqrt(DH) = 0.125, exact in tf32)
    const float* Qbh = Q + ((size_t)bh * Sv + qbase) * DHv;
    #pragma unroll
    for (int e = 0; e < 4; e++) {
        int lin = tid + e * 256;
        int row = lin >> 4, c4 = (lin & 15) * 4;
        float4 v = *(const float4*)(Qbh + row * DHv + c4);
        v.x *= 0.125f; v.y *= 0.125f; v.z *= 0.125f; v.w *= 0.125f;
        *(float4*)&Qs[row * KVP + c4] = v;
    }
    __syncthreads();

    // Preload Q fragments (A operand), constant across K-tiles
    uint32_t qf[8][4];
    #pragma unroll
    for (int ks = 0; ks < 8; ks++) {
        const uint32_t* p = (const uint32_t*)&Qs[(m0 + r) * KVP + ks * 8 + c];
        qf[ks][0] = p[0];
        qf[ks][1] = p[8 * KVP];
        qf[ks][2] = p[4];
        qf[ks][3] = p[8 * KVP + 4];
    }

    float accO[4][4];
    #pragma unroll
    for (int nt = 0; nt < 4; nt++)
        #pragma unroll
        for (int i = 0; i < 4; i++) accO[nt][i] = 0.f;
    float mrow0 = -1e30f, mrow1 = -1e30f, lrow0 = 0.f, lrow1 = 0.f;

    const uint32_t ksb = smem_u32(Ks), vsb = smem_u32(Vs);
    const float* Kbh = Kg + (size_t)bh * Sv * DHv;
    const float* Vbh = Vg + (size_t)bh * Sv * DHv;

    for (int kt = 0; kt < Sv; kt += 64) {
        __syncthreads();   // everyone done with Ks/Vs/Ps from previous tile
        #pragma unroll
        for (int e = 0; e < 4; e++) {
            int lin = tid + e * 256;
            int row = lin >> 4, c4 = (lin & 15) * 4;
            uint32_t off = (uint32_t)(row * KVP + c4) * 4;
            asm volatile("cp.async.cg.shared.global [%0], [%1], 16;"
                         :: "r"(ksb + off), "l"(Kbh + (size_t)(kt + row) * DHv + c4));
            asm volatile("cp.async.cg.shared.global [%0], [%1], 16;"
                         :: "r"(vsb + off), "l"(Vbh + (size_t)(kt + row) * DHv + c4));
        }
        asm volatile("cp.async.commit_group;" ::: "memory");
        asm volatile("cp.async.wait_group 0;" ::: "memory");
        __syncthreads();

        // S = Q @ K^T  (warp covers rows m0..m0+15, keys wn*32..+31)
        float sacc[4][4];
        #pragma unroll
        for (int nt = 0; nt < 4; nt++)
            #pragma unroll
            for (int i = 0; i < 4; i++) sacc[nt][i] = 0.f;
        #pragma unroll
        for (int ks = 0; ks < 8; ks++) {
            uint32_t bf[4][2];
            #pragma unroll
            for (int nt = 0; nt < 4; nt++) {
                const uint32_t* p = (const uint32_t*)&Ks[(wn * 32 + nt * 8 + r) * KVP + ks * 8 + c];
                bf[nt][0] = p[0];
                bf[nt][1] = p[4];
            }
            #pragma unroll
            for (int nt = 0; nt < 4; nt++)
                mma_tf32_16x8x8(sacc[nt], qf[ks], bf[nt]);
        }

        // Row max (thread-local 8 vals -> c-group shfl -> cross-warp smem)
        float mx0 = sacc[0][0], mx1 = sacc[0][2];
        #pragma unroll
        for (int nt = 0; nt < 4; nt++) {
            mx0 = fmaxf(mx0, fmaxf(sacc[nt][0], sacc[nt][1]));
            mx1 = fmaxf(mx1, fmaxf(sacc[nt][2], sacc[nt][3]));
        }
        mx0 = fmaxf(mx0, __shfl_xor_sync(0xFFFFFFFFu, mx0, 1));
        mx0 = fmaxf(mx0, __shfl_xor_sync(0xFFFFFFFFu, mx0, 2));
        mx1 = fmaxf(mx1, __shfl_xor_sync(0xFFFFFFFFu, mx1, 1));
        mx1 = fmaxf(mx1, __shfl_xor_sync(0xFFFFFFFFu, mx1, 2));
        if (c == 0) {
            redm[wn * 64 + m0 + r]     = mx0;
            redm[wn * 64 + m0 + r + 8] = mx1;
        }
        __syncthreads();
        float mn0 = fmaxf(mrow0, fmaxf(redm[m0 + r],     redm[64 + m0 + r]));
        float mn1 = fmaxf(mrow1, fmaxf(redm[m0 + r + 8], redm[64 + m0 + r + 8]));

        // exp, store P (tf32-rounded), partial row sums
        float sum0 = 0.f, sum1 = 0.f;
        #pragma unroll
        for (int nt = 0; nt < 4; nt++) {
            float p00 = __expf(sacc[nt][0] - mn0);
            float p01 = __expf(sacc[nt][1] - mn0);
            float p10 = __expf(sacc[nt][2] - mn1);
            float p11 = __expf(sacc[nt][3] - mn1);
            sum0 += p00 + p01;
            sum1 += p10 + p11;
            int col = wn * 32 + nt * 8 + 2 * c;
            *(float2*)&Ps[(m0 + r) * PP + col]     = make_float2(rtf32(p00), rtf32(p01));
            *(float2*)&Ps[(m0 + r + 8) * PP + col] = make_float2(rtf32(p10), rtf32(p11));
        }
        sum0 += __shfl_xor_sync(0xFFFFFFFFu, sum0, 1);
        sum0 += __shfl_xor_sync(0xFFFFFFFFu, sum0, 2);
        sum1 += __shfl_xor_sync(0xFFFFFFFFu, sum1, 1);
        sum1 += __shfl_xor_sync(0xFFFFFFFFu, sum1, 2);
        if (c == 0) {
            redl[wn * 64 + m0 + r]     = sum0;
            redl[wn * 64 + m0 + r + 8] = sum1;
        }
        // Rescale running output
        float cor0 = __expf(mrow0 - mn0), cor1 = __expf(mrow1 - mn1);
        mrow0 = mn0; mrow1 = mn1;
        #pragma unroll
        for (int nt = 0; nt < 4; nt++) {
            accO[nt][0] *= cor0; accO[nt][1] *= cor0;
            accO[nt][2] *= cor1; accO[nt][3] *= cor1;
        }
        __syncthreads();
        lrow0 = lrow0 * cor0 + redl[m0 + r]     + redl[64 + m0 + r];
        lrow1 = lrow1 * cor1 + redl[m0 + r + 8] + redl[64 + m0 + r + 8];

        // O += P @ V  (warp covers rows m0..m0+15, dims wn*32..+31)
        #pragma unroll
        for (int ks = 0; ks < 8; ks++) {
            uint32_t pf[4];
            {
                const uint32_t* p = (const uint32_t*)&Ps[(m0 + r) * PP + ks * 8 + c];
                pf[0] = p[0];
                pf[1] = p[8 * PP];
                pf[2] = p[4];
                pf[3] = p[8 * PP + 4];
            }
            uint32_t vb[4][2];
            #pragma unroll
            for (int nt = 0; nt < 4; nt++) {
                const uint32_t* p = (const uint32_t*)&Vs[(ks * 8 + c) * KVP + wn * 32 + nt * 8 + r];
                vb[nt][0] = p[0];
                vb[nt][1] = p[4 * KVP];
            }
            #pragma unroll
            for (int nt = 0; nt < 4; nt++)
                mma_tf32_16x8x8(accO[nt], pf, vb[nt]);
        }
    }

    // Output: ctx[b, q, h*64 + d] = accO / l  (tf32-rounded: Wo GEMM A operand)
    float il0 = 1.0f / lrow0, il1 = 1.0f / lrow1;
    #pragma unroll
    for (int nt = 0; nt < 4; nt++) {
        int d0 = wn * 32 + nt * 8 + 2 * c;
        int row0 = qbase + m0 + r, row1 = row0 + 8;
        size_t a0 = ((size_t)b * Sv + row0) * Dv + h * DHv + d0;
        size_t a1 = ((size_t)b * Sv + row1) * Dv + h * DHv + d0;
        *(float2*)&ctx[a0] = make_float2(rtf32(accO[nt][0] * il0), rtf32(accO[nt][1] * il0));
        *(float2*)&ctx[a1] = make_float2(rtf32(accO[nt][2] * il1), rtf32(accO[nt][3] * il1));
    }
}

// ---------------- Masked rows (>=512): ctx = mean_k v -----------------------
__global__ __launch_bounds__(256)
void meanv_kernel(const float* __restrict__ Vg, float* __restrict__ ctx) {
    const int h = blockIdx.x, b = blockIdx.y;
    const int bh = b * Hv + h;
    const int tid = threadIdx.x;
    const int d = tid & 63, slice = tid >> 6;
    const float* Vbh = Vg + (size_t)bh * Sv * DHv;
    float s = 0.f;
    for (int k = slice * 256; k < slice * 256 + 256; k++)
        s += Vbh[k * DHv + d];
    __shared__ float red[4][64];
    __shared__ float mv[64];
    red[slice][d] = s;
    __syncthreads();
    if (tid < 64)
        mv[tid] = rtf32((red[0][tid] + red[1][tid] + red[2][tid] + red[3][tid]) * (1.0f / Sv));
    __syncthreads();
    float val = mv[d];
    for (int r = slice; r < 512; r += 4)
        ctx[((size_t)b * Sv + 512 + r) * Dv + h * DHv + d] = val;
}

// ---------------- driver -----------------------------------------------------
extern "C" void kernel_launch(void* const* d_in, const int* in_sizes, int n_in,
                              void* d_out, int out_size) {
    const float* x    = (const float*)d_in[0];
    const float* Wq   = (const float*)d_in[1];
    const float* bq   = (const float*)d_in[2];
    const float* Wk   = (const float*)d_in[3];
    const float* bk   = (const float*)d_in[4];
    const float* Wv   = (const float*)d_in[5];
    const float* bv   = (const float*)d_in[6];
    const float* Wo   = (const float*)d_in[7];
    const float* bo   = (const float*)d_in[8];
    const float* ln1g = (const float*)d_in[9];
    const float* ln1b = (const float*)d_in[10];
    const float* ln2g = (const float*)d_in[11];
    const float* ln2b = (const float*)d_in[12];
    const float* W1   = (const float*)d_in[13];
    const float* b1   = (const float*)d_in[14];
    const float* W2   = (const float*)d_in[15];
    const float* b2   = (const float*)d_in[16];
    float* out = (float*)d_out;

    float *xn, *q, *k, *v, *ctx, *x2, *xn2, *h1;
    float *wqT, *wkT, *wvT, *woT, *w1T, *w2T;
    cudaGetSymbolAddress((void**)&xn,  g_xn);
    cudaGetSymbolAddress((void**)&q,   g_q);
    cudaGetSymbolAddress((void**)&k,   g_k);
    cudaGetSymbolAddress((void**)&v,   g_v);
    cudaGetSymbolAddress((void**)&ctx, g_ctx);
    cudaGetSymbolAddress((void**)&x2,  g_x2);
    cudaGetSymbolAddress((void**)&xn2, g_xn2);
    cudaGetSymbolAddress((void**)&h1,  g_h1);
    cudaGetSymbolAddress((void**)&wqT, g_wqT);
    cudaGetSymbolAddress((void**)&wkT, g_wkT);
    cudaGetSymbolAddress((void**)&wvT, g_wvT);
    cudaGetSymbolAddress((void**)&woT, g_woT);
    cudaGetSymbolAddress((void**)&w1T, g_w1T);
    cudaGetSymbolAddress((void**)&w2T, g_w2T);

    cudaFuncSetAttribute(tgemm<1>, cudaFuncAttributeMaxDynamicSharedMemorySize, SMEMSZ);
    cudaFuncSetAttribute(tgemm<2>, cudaFuncAttributeMaxDynamicSharedMemorySize, SMEMSZ);
    cudaFuncSetAttribute(tgemm<3>, cudaFuncAttributeMaxDynamicSharedMemorySize, SMEMSZ);
    cudaFuncSetAttribute(attn_mma, cudaFuncAttributeMaxDynamicSharedMemorySize, ATTN_SMEM);

    // Weight transposes (rounded to tf32)
    transpose_round<<<dim3(Dv/32,   Dv/32),   256>>>(Wq, wqT, Dv,   Dv);
    transpose_round<<<dim3(Dv/32,   Dv/32),   256>>>(Wk, wkT, Dv,   Dv);
    transpose_round<<<dim3(Dv/32,   Dv/32),   256>>>(Wv, wvT, Dv,   Dv);
    transpose_round<<<dim3(Dv/32,   Dv/32),   256>>>(Wo, woT, Dv,   Dv);
    transpose_round<<<dim3(MLPv/32, Dv/32),   256>>>(W1, w1T, Dv,   MLPv);
    transpose_round<<<dim3(Dv/32,   MLPv/32), 256>>>(W2, w2T, MLPv, Dv);

    // 1. LN1
    ln_kernel<<<ROWS, 256>>>(x, ln1g, ln1b, xn);

    // 2. QKV projections (tensor core, scatter into [B,H,S,64], tf32-rounded).
    //    Q only needed for query rows < 512 of each batch -> half M with tile remap.
    dim3 gD(Dv/128, ROWS/128);             // (6, 64)
    dim3 gQ(Dv/128, ROWS/256);             // (6, 32) remapped
    tgemm<3><<<gQ, 256, SMEMSZ>>>(xn, wqT, bq, nullptr, q, ROWS, Dv, Dv, 1);
    tgemm<3><<<gD, 256, SMEMSZ>>>(xn, wkT, bk, nullptr, k, ROWS, Dv, Dv, 0);
    tgemm<3><<<gD, 256, SMEMSZ>>>(xn, wvT, bv, nullptr, v, ROWS, Dv, Dv, 0);

    // 3. Attention (tensor-core flash) + masked-row mean
    attn_mma<<<dim3(8, Hv, Bv), 256, ATTN_SMEM>>>(q, k, v, ctx);
    meanv_kernel<<<dim3(Hv, Bv), 256>>>(v, ctx);

    // 4. Output projection + residual
    tgemm<1><<<gD, 256, SMEMSZ>>>(ctx, woT, bo, x, x2, ROWS, Dv, Dv, 0);

    // 5. LN2
    ln_kernel<<<ROWS, 256>>>(x2, ln2g, ln2b, xn2);

    // 6. MLP
    dim3 gM(MLPv/128, ROWS/128);           // (24, 64)
    tgemm<2><<<gM, 256, SMEMSZ>>>(xn2, w1T, b1, nullptr, h1, ROWS, MLPv, Dv, 0);
    tgemm<1><<<gD, 256, SMEMSZ>>>(h1, w2T, b2, x2, out, ROWS, Dv, MLPv, 0);
}

// round 12
// speedup vs baseline: 2.4882x; 1.7220x over previous
#include <cuda_runtime.h>
#include <cuda_fp16.h>
#include <cstdint>

// Problem constants
#define Bv   8
#define Sv   1024
#define Dv   768
#define Hv   12
#define DHv  64
#define MLPv 3072
#define ROWS (Bv*Sv)            // 8192

// fp16 GEMM tiling
#define BKh      64                      // K halves per chunk
#define LDKh     72                      // 64 + 8 pad (144B row stride: ldmatrix conflict-free)
#define STAGE_H  (128*LDKh)              // halves per operand per stage
#define SMEMSZ   (6*STAGE_H*2)           // 3 stages x (A,B) halves = 110592 B

// Attention tiling (tf32 path, unchanged)
#define KVP  72
#define PP   68
#define ATTN_SMEM ((3*64*KVP + 64*PP + 256) * 4)   // 73728 B

// ---------------- scratch (static device memory; no allocs) ----------------
__device__ __half g_xnh [ROWS*Dv];
__device__ float  g_q   [ROWS*Dv];
__device__ float  g_k   [ROWS*Dv];
__device__ float  g_v   [ROWS*Dv];
__device__ __half g_ctxh[ROWS*Dv];
__device__ float  g_x2  [ROWS*Dv];
__device__ __half g_xn2h[ROWS*Dv];
__device__ __half g_h1h [ROWS*MLPv];
__device__ __half g_wqT[Dv*Dv];
__device__ __half g_wkT[Dv*Dv];
__device__ __half g_wvT[Dv*Dv];
__device__ __half g_woT[Dv*Dv];
__device__ __half g_w1T[MLPv*Dv];   // [3072, 768]
__device__ __half g_w2T[Dv*MLPv];   // [768, 3072]

// ---------------- helpers ----------------------------------------------------
__device__ __forceinline__ uint32_t smem_u32(const void* p) {
    uint32_t a;
    asm("{ .reg .u64 t; cvta.to.shared.u64 t, %1; cvt.u32.u64 %0, t; }" : "=r"(a) : "l"(p));
    return a;
}
__device__ __forceinline__ float rtf32(float x) {   // round-to-nearest tf32
    uint32_t u; asm("cvt.rna.tf32.f32 %0, %1;" : "=r"(u) : "f"(x));
    return __uint_as_float(u);
}
__device__ __forceinline__ uint32_t h2_bits(__half2 h) {   // bitcast __half2 -> u32
    uint32_t u; *(__half2*)&u = h; return u;
}
__device__ __forceinline__ void mma_tf32_16x8x8(float* d, const uint32_t* a, const uint32_t* b) {
    asm volatile(
        "mma.sync.aligned.m16n8k8.row.col.f32.tf32.tf32.f32 "
        "{%0,%1,%2,%3}, {%4,%5,%6,%7}, {%8,%9}, {%0,%1,%2,%3};"
        : "+f"(d[0]), "+f"(d[1]), "+f"(d[2]), "+f"(d[3])
        : "r"(a[0]), "r"(a[1]), "r"(a[2]), "r"(a[3]), "r"(b[0]), "r"(b[1]));
}
__device__ __forceinline__ void mma_f16_16x8x16(float* d, const uint32_t* a, const uint32_t* b) {
    asm volatile(
        "mma.sync.aligned.m16n8k16.row.col.f32.f16.f16.f32 "
        "{%0,%1,%2,%3}, {%4,%5,%6,%7}, {%8,%9}, {%0,%1,%2,%3};"
        : "+f"(d[0]), "+f"(d[1]), "+f"(d[2]), "+f"(d[3])
        : "r"(a[0]), "r"(a[1]), "r"(a[2]), "r"(a[3]), "r"(b[0]), "r"(b[1]));
}
#define LDSM4(R, ADDR) \
    asm volatile("ldmatrix.sync.aligned.m8n8.x4.shared.b16 {%0,%1,%2,%3}, [%4];" \
        : "=r"((R)[0]), "=r"((R)[1]), "=r"((R)[2]), "=r"((R)[3]) : "r"(ADDR))
#define LDSM2(R, ADDR) \
    asm volatile("ldmatrix.sync.aligned.m8n8.x2.shared.b16 {%0,%1}, [%2];" \
        : "=r"((R)[0]), "=r"((R)[1]) : "r"(ADDR))

// ---------------- weight transpose + convert to fp16 -------------------------
// W [Kd, Nd] row-major  ->  WT [Nd, Kd] fp16
__global__ __launch_bounds__(256)
void transpose_half(const float* __restrict__ W, __half* __restrict__ WT, int Kd, int Nd) {
    __shared__ float t[32][33];
    int n0 = blockIdx.x * 32, k0 = blockIdx.y * 32;
    int tx = threadIdx.x & 31, ty = threadIdx.x >> 5;  // 32 x 8
    #pragma unroll
    for (int i = 0; i < 32; i += 8)
        t[ty + i][tx] = W[(size_t)(k0 + ty + i) * Nd + n0 + tx];
    __syncthreads();
    #pragma unroll
    for (int i = 0; i < 32; i += 8)
        WT[(size_t)(n0 + ty + i) * Kd + k0 + tx] = __float2half_rn(t[tx][ty + i]);
}

// ---------------- LayerNorm -> fp16 output (GEMM A operand) ------------------
__global__ __launch_bounds__(256)
void ln_kernel(const float* __restrict__ x, const float* __restrict__ g,
               const float* __restrict__ b, __half* __restrict__ y) {
    int row = blockIdx.x;
    int t = threadIdx.x;
    const float* xr = x + (size_t)row * Dv;
    float v0 = xr[t], v1 = xr[t + 256], v2 = xr[t + 512];
    float s  = v0 + v1 + v2;
    float s2 = v0*v0 + v1*v1 + v2*v2;
    #pragma unroll
    for (int o = 16; o; o >>= 1) {
        s  += __shfl_xor_sync(0xFFFFFFFFu, s,  o);
        s2 += __shfl_xor_sync(0xFFFFFFFFu, s2, o);
    }
    __shared__ float rs[8], rs2[8];
    int w = t >> 5, lane = t & 31;
    if (lane == 0) { rs[w] = s; rs2[w] = s2; }
    __syncthreads();
    float tot = 0.f, tot2 = 0.f;
    #pragma unroll
    for (int i = 0; i < 8; i++) { tot += rs[i]; tot2 += rs2[i]; }
    float mu  = tot * (1.0f / Dv);
    float var = tot2 * (1.0f / Dv) - mu * mu;
    float inv = rsqrtf(var + 1e-6f);
    __half* yr = y + (size_t)row * Dv;
    yr[t]       = __float2half_rn((v0 - mu) * inv * g[t]       + b[t]);
    yr[t + 256] = __float2half_rn((v1 - mu) * inv * g[t + 256] + b[t + 256]);
    yr[t + 512] = __float2half_rn((v2 - mu) * inv * g[t + 512] + b[t + 512]);
}

// ---------------- fp16 tensor-core GEMM: C[M,N] = A[M,K] @ B[N,K]^T ----------
// EPI: 1 = +bias +res, fp32 out ; 2 = +bias, relu, fp16 out ;
//      3 = +bias, round-tf32, fp32 scatter [B,H,S,64]
template<int EPI>
__global__ __launch_bounds__(256, 2)
void hgemm(const __half* __restrict__ A, const __half* __restrict__ Bw,
           const float* __restrict__ bias, const float* __restrict__ res,
           void* __restrict__ Cout, int M, int N, int K, int mremap) {
    extern __shared__ __half hsm[];
    __half* sA = hsm;                        // [3][128][LDKh]
    __half* sB = hsm + 3 * STAGE_H;
    const uint32_t saA = smem_u32(sA);
    const uint32_t saB = smem_u32(sB);

    const int tid = threadIdx.x;
    int by = blockIdx.y;
    if (mremap) by = (by >> 2) * 8 + (by & 3);
    const int rowBase = by * 128, colBase = blockIdx.x * 128;
    const int warp = tid >> 5, lane = tid & 31;
    const int wm = warp >> 2, wn = warp & 3;     // warps: 2 (m) x 4 (n)

    auto load = [&](int j, int s) {
        int k0 = j * BKh;
        #pragma unroll
        for (int e = 0; e < 4; e++) {
            int idx = tid + 256 * e;             // 0..1023
            int row = idx >> 3, kc = (idx & 7) * 8;
            const __half* ga = A  + (size_t)(rowBase + row) * K + k0 + kc;
            const __half* gb = Bw + (size_t)(colBase + row) * K + k0 + kc;
            uint32_t da = saA + (uint32_t)(s * STAGE_H + row * LDKh + kc) * 2;
            uint32_t db = saB + (uint32_t)(s * STAGE_H + row * LDKh + kc) * 2;
            asm volatile("cp.async.cg.shared.global [%0], [%1], 16;" :: "r"(da), "l"(ga));
            asm volatile("cp.async.cg.shared.global [%0], [%1], 16;" :: "r"(db), "l"(gb));
        }
        asm volatile("cp.async.commit_group;" ::: "memory");
    };

    float acc[4][4][4];
    #pragma unroll
    for (int mt = 0; mt < 4; mt++)
        #pragma unroll
        for (int nt = 0; nt < 4; nt++)
            #pragma unroll
            for (int i = 0; i < 4; i++) acc[mt][nt][i] = 0.f;

    load(0, 0);
    load(1, 1);

    // Per-lane ldmatrix byte offsets (within a stage)
    const int arow = lane & 15;                  // A: lanes 0-15 rows, 16-31 same rows col+8
    const int acol = (lane < 16) ? 0 : 8;
    uint32_t aoff[4], boff[4];
    #pragma unroll
    for (int mt = 0; mt < 4; mt++)
        aoff[mt] = (uint32_t)((wm * 64 + mt * 16 + arow) * LDKh + acol) * 2;
    const int bl = lane & 15;
    #pragma unroll
    for (int nt = 0; nt < 4; nt++)
        boff[nt] = (uint32_t)((wn * 32 + nt * 8 + (bl & 7)) * LDKh + (bl >> 3) * 8) * 2;

    const int nch = K / BKh;
    for (int i = 0; i < nch; i++) {
        if (i + 2 < nch) load(i + 2, (i + 2) % 3);
        else asm volatile("cp.async.commit_group;" ::: "memory");
        asm volatile("cp.async.wait_group 2;" ::: "memory");
        __syncthreads();

        const uint32_t aS = saA + (uint32_t)((i % 3) * STAGE_H) * 2;
        const uint32_t bS = saB + (uint32_t)((i % 3) * STAGE_H) * 2;

        #pragma unroll
        for (int ks = 0; ks < 4; ks++) {          // 4 x k16 = BKh
            uint32_t af[4][4], bf[4][2];
            #pragma unroll
            for (int mt = 0; mt < 4; mt++) LDSM4(af[mt], aS + aoff[mt] + ks * 32);
            #pragma unroll
            for (int nt = 0; nt < 4; nt++) LDSM2(bf[nt], bS + boff[nt] + ks * 32);
            #pragma unroll
            for (int mt = 0; mt < 4; mt++)
                #pragma unroll
                for (int nt = 0; nt < 4; nt++)
                    mma_f16_16x8x16(acc[mt][nt], af[mt], bf[nt]);
        }
        __syncthreads();
    }

    // Epilogue: regs -> smem tile -> coalesced stores
    float* tile = (float*)hsm;                // [128][132]
    const int r = lane >> 2, c = lane & 3;
    #pragma unroll
    for (int mt = 0; mt < 4; mt++)
        #pragma unroll
        for (int nt = 0; nt < 4; nt++) {
            int r0 = wm * 64 + mt * 16 + r;
            int c0 = wn * 32 + nt * 8 + 2 * c;
            tile[r0 * 132 + c0]           = acc[mt][nt][0];
            tile[r0 * 132 + c0 + 1]       = acc[mt][nt][1];
            tile[(r0 + 8) * 132 + c0]     = acc[mt][nt][2];
            tile[(r0 + 8) * 132 + c0 + 1] = acc[mt][nt][3];
        }
    __syncthreads();

    float4 b4 = *(const float4*)(bias + colBase + lane * 4);
    int col0 = colBase + lane * 4;
    int hh = col0 >> 6, dd = col0 & 63;          // for EPI==3
    #pragma unroll
    for (int rr = 0; rr < 16; rr++) {
        int trow = warp * 16 + rr;
        int row  = rowBase + trow;
        float4 v = *(float4*)&tile[trow * 132 + lane * 4];
        v.x += b4.x; v.y += b4.y; v.z += b4.z; v.w += b4.w;
        if (EPI == 1) {
            float4 r4 = *(const float4*)(res + (size_t)row * N + col0);
            v.x += r4.x; v.y += r4.y; v.z += r4.z; v.w += r4.w;
            *(float4*)&((float*)Cout)[(size_t)row * N + col0] = v;
        }
        if (EPI == 2) {
            __half2 h01 = __floats2half2_rn(fmaxf(v.x, 0.f), fmaxf(v.y, 0.f));
            __half2 h23 = __floats2half2_rn(fmaxf(v.z, 0.f), fmaxf(v.w, 0.f));
            uint2 u = make_uint2(h2_bits(h01), h2_bits(h23));
            *(uint2*)&((__half*)Cout)[(size_t)row * N + col0] = u;
        }
        if (EPI == 3) {
            v.x = rtf32(v.x); v.y = rtf32(v.y); v.z = rtf32(v.z); v.w = rtf32(v.w);
            int bb = row >> 10, ss = row & 1023;
            *(float4*)&((float*)Cout)[(((size_t)(bb * Hv + hh) * Sv + ss) * DHv) + dd] = v;
        }
    }
}

// ---------------- Attention (query rows < 512) via tf32 MMA flash -----------
// grid (8 qtiles, H, B), 256 threads = 8 warps = 4(m) x 2(n)
__global__ __launch_bounds__(256, 2)
void attn_mma(const float* __restrict__ Q, const float* __restrict__ Kg,
              const float* __restrict__ Vg, __half* __restrict__ ctx) {
    extern __shared__ float sm[];
    float* Qs   = sm;                     // [64][KVP]
    float* Ks   = Qs + 64 * KVP;          // [64][KVP]
    float* Vs   = Ks + 64 * KVP;          // [64][KVP]
    float* Ps   = Vs + 64 * KVP;          // [64][PP]
    float* redm = Ps + 64 * PP;           // [2][64]
    float* redl = redm + 128;             // [2][64]

    const int b = blockIdx.z, h = blockIdx.y;
    const int bh = b * Hv + h;
    const int qbase = blockIdx.x * 64;
    const int tid = threadIdx.x, warp = tid >> 5, lane = tid & 31;
    const int wm = warp >> 1, wn = warp & 1;
    const int r = lane >> 2, c = lane & 3;
    const int m0 = wm * 16;

    const float* Qbh = Q + ((size_t)bh * Sv + qbase) * DHv;
    #pragma unroll
    for (int e = 0; e < 4; e++) {
        int lin = tid + e * 256;
        int row = lin >> 4, c4 = (lin & 15) * 4;
        float4 v = *(const float4*)(Qbh + row * DHv + c4);
        v.x *= 0.125f; v.y *= 0.125f; v.z *= 0.125f; v.w *= 0.125f;
        *(float4*)&Qs[row * KVP + c4] = v;
    }
    __syncthreads();

    uint32_t qf[8][4];
    #pragma unroll
    for (int ks = 0; ks < 8; ks++) {
        const uint32_t* p = (const uint32_t*)&Qs[(m0 + r) * KVP + ks * 8 + c];
        qf[ks][0] = p[0];
        qf[ks][1] = p[8 * KVP];
        qf[ks][2] = p[4];
        qf[ks][3] = p[8 * KVP + 4];
    }

    float accO[4][4];
    #pragma unroll
    for (int nt = 0; nt < 4; nt++)
        #pragma unroll
        for (int i = 0; i < 4; i++) accO[nt][i] = 0.f;
    float mrow0 = -1e30f, mrow1 = -1e30f, lrow0 = 0.f, lrow1 = 0.f;

    const uint32_t ksb = smem_u32(Ks), vsb = smem_u32(Vs);
    const float* Kbh = Kg + (size_t)bh * Sv * DHv;
    const float* Vbh = Vg + (size_t)bh * Sv * DHv;

    for (int kt = 0; kt < Sv; kt += 64) {
        __syncthreads();
        #pragma unroll
        for (int e = 0; e < 4; e++) {
            int lin = tid + e * 256;
            int row = lin >> 4, c4 = (lin & 15) * 4;
            uint32_t off = (uint32_t)(row * KVP + c4) * 4;
            asm volatile("cp.async.cg.shared.global [%0], [%1], 16;"
                         :: "r"(ksb + off), "l"(Kbh + (size_t)(kt + row) * DHv + c4));
            asm volatile("cp.async.cg.shared.global [%0], [%1], 16;"
                         :: "r"(vsb + off), "l"(Vbh + (size_t)(kt + row) * DHv + c4));
        }
        asm volatile("cp.async.commit_group;" ::: "memory");
        asm volatile("cp.async.wait_group 0;" ::: "memory");
        __syncthreads();

        float sacc[4][4];
        #pragma unroll
        for (int nt = 0; nt < 4; nt++)
            #pragma unroll
            for (int i = 0; i < 4; i++) sacc[nt][i] = 0.f;
        #pragma unroll
        for (int ks = 0; ks < 8; ks++) {
            uint32_t bf[4][2];
            #pragma unroll
            for (int nt = 0; nt < 4; nt++) {
                const uint32_t* p = (const uint32_t*)&Ks[(wn * 32 + nt * 8 + r) * KVP + ks * 8 + c];
                bf[nt][0] = p[0];
                bf[nt][1] = p[4];
            }
            #pragma unroll
            for (int nt = 0; nt < 4; nt++)
                mma_tf32_16x8x8(sacc[nt], qf[ks], bf[nt]);
        }

        float mx0 = sacc[0][0], mx1 = sacc[0][2];
        #pragma unroll
        for (int nt = 0; nt < 4; nt++) {
            mx0 = fmaxf(mx0, fmaxf(sacc[nt][0], sacc[nt][1]));
            mx1 = fmaxf(mx1, fmaxf(sacc[nt][2], sacc[nt][3]));
        }
        mx0 = fmaxf(mx0, __shfl_xor_sync(0xFFFFFFFFu, mx0, 1));
        mx0 = fmaxf(mx0, __shfl_xor_sync(0xFFFFFFFFu, mx0, 2));
        mx1 = fmaxf(mx1, __shfl_xor_sync(0xFFFFFFFFu, mx1, 1));
        mx1 = fmaxf(mx1, __shfl_xor_sync(0xFFFFFFFFu, mx1, 2));
        if (c == 0) {
            redm[wn * 64 + m0 + r]     = mx0;
            redm[wn * 64 + m0 + r + 8] = mx1;
        }
        __syncthreads();
        float mn0 = fmaxf(mrow0, fmaxf(redm[m0 + r],     redm[64 + m0 + r]));
        float mn1 = fmaxf(mrow1, fmaxf(redm[m0 + r + 8], redm[64 + m0 + r + 8]));

        float sum0 = 0.f, sum1 = 0.f;
        #pragma unroll
        for (int nt = 0; nt < 4; nt++) {
            float p00 = __expf(sacc[nt][0] - mn0);
            float p01 = __expf(sacc[nt][1] - mn0);
            float p10 = __expf(sacc[nt][2] - mn1);
            float p11 = __expf(sacc[nt][3] - mn1);
            sum0 += p00 + p01;
            sum1 += p10 + p11;
            int col = wn * 32 + nt * 8 + 2 * c;
            *(float2*)&Ps[(m0 + r) * PP + col]     = make_float2(rtf32(p00), rtf32(p01));
            *(float2*)&Ps[(m0 + r + 8) * PP + col] = make_float2(rtf32(p10), rtf32(p11));
        }
        sum0 += __shfl_xor_sync(0xFFFFFFFFu, sum0, 1);
        sum0 += __shfl_xor_sync(0xFFFFFFFFu, sum0, 2);
        sum1 += __shfl_xor_sync(0xFFFFFFFFu, sum1, 1);
        sum1 += __shfl_xor_sync(0xFFFFFFFFu, sum1, 2);
        if (c == 0) {
            redl[wn * 64 + m0 + r]     = sum0;
            redl[wn * 64 + m0 + r + 8] = sum1;
        }
        float cor0 = __expf(mrow0 - mn0), cor1 = __expf(mrow1 - mn1);
        mrow0 = mn0; mrow1 = mn1;
        #pragma unroll
        for (int nt = 0; nt < 4; nt++) {
            accO[nt][0] *= cor0; accO[nt][1] *= cor0;
            accO[nt][2] *= cor1; accO[nt][3] *= cor1;
        }
        __syncthreads();
        lrow0 = lrow0 * cor0 + redl[m0 + r]     + redl[64 + m0 + r];
        lrow1 = lrow1 * cor1 + redl[m0 + r + 8] + redl[64 + m0 + r + 8];

        #pragma unroll
        for (int ks = 0; ks < 8; ks++) {
            uint32_t pf[4];
            {
                const uint32_t* p = (const uint32_t*)&Ps[(m0 + r) * PP + ks * 8 + c];
                pf[0] = p[0];
                pf[1] = p[8 * PP];
                pf[2] = p[4];
                pf[3] = p[8 * PP + 4];
            }
            uint32_t vb[4][2];
            #pragma unroll
            for (int nt = 0; nt < 4; nt++) {
                const uint32_t* p = (const uint32_t*)&Vs[(ks * 8 + c) * KVP + wn * 32 + nt * 8 + r];
                vb[nt][0] = p[0];
                vb[nt][1] = p[4 * KVP];
            }
            #pragma unroll
            for (int nt = 0; nt < 4; nt++)
                mma_tf32_16x8x8(accO[nt], pf, vb[nt]);
        }
    }

    float il0 = 1.0f / lrow0, il1 = 1.0f / lrow1;
    #pragma unroll
    for (int nt = 0; nt < 4; nt++) {
        int d0 = wn * 32 + nt * 8 + 2 * c;
        int row0 = qbase + m0 + r, row1 = row0 + 8;
        size_t a0 = ((size_t)b * Sv + row0) * Dv + h * DHv + d0;
        size_t a1 = ((size_t)b * Sv + row1) * Dv + h * DHv + d0;
        *(__half2*)&ctx[a0] = __floats2half2_rn(accO[nt][0] * il0, accO[nt][1] * il0);
        *(__half2*)&ctx[a1] = __floats2half2_rn(accO[nt][2] * il1, accO[nt][3] * il1);
    }
}

// ---------------- Masked rows (>=512): ctx = mean_k v -----------------------
__global__ __launch_bounds__(256)
void meanv_kernel(const float* __restrict__ Vg, __half* __restrict__ ctx) {
    const int h = blockIdx.x, b = blockIdx.y;
    const int bh = b * Hv + h;
    const int tid = threadIdx.x;
    const int d = tid & 63, slice = tid >> 6;
    const float* Vbh = Vg + (size_t)bh * Sv * DHv;
    float s = 0.f;
    for (int k = slice * 256; k < slice * 256 + 256; k++)
        s += Vbh[k * DHv + d];
    __shared__ float red[4][64];
    __shared__ __half mv[64];
    red[slice][d] = s;
    __syncthreads();
    if (tid < 64)
        mv[tid] = __float2half_rn((red[0][tid] + red[1][tid] + red[2][tid] + red[3][tid]) * (1.0f / Sv));
    __syncthreads();
    __half val = mv[d];
    for (int r = slice; r < 512; r += 4)
        ctx[((size_t)b * Sv + 512 + r) * Dv + h * DHv + d] = val;
}

// ---------------- driver -----------------------------------------------------
extern "C" void kernel_launch(void* const* d_in, const int* in_sizes, int n_in,
                              void* d_out, int out_size) {
    const float* x    = (const float*)d_in[0];
    const float* Wq   = (const float*)d_in[1];
    const float* bq   = (const float*)d_in[2];
    const float* Wk   = (const float*)d_in[3];
    const float* bk   = (const float*)d_in[4];
    const float* Wv   = (const float*)d_in[5];
    const float* bv   = (const float*)d_in[6];
    const float* Wo   = (const float*)d_in[7];
    const float* bo   = (const float*)d_in[8];
    const float* ln1g = (const float*)d_in[9];
    const float* ln1b = (const float*)d_in[10];
    const float* ln2g = (const float*)d_in[11];
    const float* ln2b = (const float*)d_in[12];
    const float* W1   = (const float*)d_in[13];
    const float* b1   = (const float*)d_in[14];
    const float* W2   = (const float*)d_in[15];
    const float* b2   = (const float*)d_in[16];
    float* out = (float*)d_out;

    __half *xnh, *ctxh, *xn2h, *h1h, *wqT, *wkT, *wvT, *woT, *w1T, *w2T;
    float *q, *k, *v, *x2;
    cudaGetSymbolAddress((void**)&xnh,  g_xnh);
    cudaGetSymbolAddress((void**)&q,    g_q);
    cudaGetSymbolAddress((void**)&k,    g_k);
    cudaGetSymbolAddress((void**)&v,    g_v);
    cudaGetSymbolAddress((void**)&ctxh, g_ctxh);
    cudaGetSymbolAddress((void**)&x2,   g_x2);
    cudaGetSymbolAddress((void**)&xn2h, g_xn2h);
    cudaGetSymbolAddress((void**)&h1h,  g_h1h);
    cudaGetSymbolAddress((void**)&wqT,  g_wqT);
    cudaGetSymbolAddress((void**)&wkT,  g_wkT);
    cudaGetSymbolAddress((void**)&wvT,  g_wvT);
    cudaGetSymbolAddress((void**)&woT,  g_woT);
    cudaGetSymbolAddress((void**)&w1T,  g_w1T);
    cudaGetSymbolAddress((void**)&w2T,  g_w2T);

    cudaFuncSetAttribute(hgemm<1>, cudaFuncAttributeMaxDynamicSharedMemorySize, SMEMSZ);
    cudaFuncSetAttribute(hgemm<2>, cudaFuncAttributeMaxDynamicSharedMemorySize, SMEMSZ);
    cudaFuncSetAttribute(hgemm<3>, cudaFuncAttributeMaxDynamicSharedMemorySize, SMEMSZ);
    cudaFuncSetAttribute(attn_mma, cudaFuncAttributeMaxDynamicSharedMemorySize, ATTN_SMEM);

    // Weight transposes (fp16)
    transpose_half<<<dim3(Dv/32,   Dv/32),   256>>>(Wq, wqT, Dv,   Dv);
    transpose_half<<<dim3(Dv/32,   Dv/32),   256>>>(Wk, wkT, Dv,   Dv);
    transpose_half<<<dim3(Dv/32,   Dv/32),   256>>>(Wv, wvT, Dv,   Dv);
    transpose_half<<<dim3(Dv/32,   Dv/32),   256>>>(Wo, woT, Dv,   Dv);
    transpose_half<<<dim3(MLPv/32, Dv/32),   256>>>(W1, w1T, Dv,   MLPv);
    transpose_half<<<dim3(Dv/32,   MLPv/32), 256>>>(W2, w2T, MLPv, Dv);

    // 1. LN1 -> fp16
    ln_kernel<<<ROWS, 256>>>(x, ln1g, ln1b, xnh);

    // 2. QKV projections (fp16 MMA, fp32 scatter into [B,H,S,64], tf32-rounded).
    dim3 gD(Dv/128, ROWS/128);             // (6, 64)
    dim3 gQ(Dv/128, ROWS/256);             // (6, 32) remapped: rows<512 per batch
    hgemm<3><<<gQ, 256, SMEMSZ>>>(xnh, wqT, bq, nullptr, q, ROWS, Dv, Dv, 1);
    hgemm<3><<<gD, 256, SMEMSZ>>>(xnh, wkT, bk, nullptr, k, ROWS, Dv, Dv, 0);
    hgemm<3><<<gD, 256, SMEMSZ>>>(xnh, wvT, bv, nullptr, v, ROWS, Dv, Dv, 0);

    // 3. Attention (tf32 MMA flash) + masked-row mean -> ctx fp16
    attn_mma<<<dim3(8, Hv, Bv), 256, ATTN_SMEM>>>(q, k, v, ctxh);
    meanv_kernel<<<dim3(Hv, Bv), 256>>>(v, ctxh);

    // 4. Output projection + residual (fp32 out)
    hgemm<1><<<gD, 256, SMEMSZ>>>(ctxh, woT, bo, x, x2, ROWS, Dv, Dv, 0);

    // 5. LN2 -> fp16
    ln_kernel<<<ROWS, 256>>>(x2, ln2g, ln2b, xn2h);

    // 6. MLP
    dim3 gM(MLPv/128, ROWS/128);           // (24, 64)
    hgemm<2><<<gM, 256, SMEMSZ>>>(xn2h, w1T, b1, nullptr, h1h, ROWS, MLPv, Dv, 0);
    hgemm<1><<<gD, 256, SMEMSZ>>>(h1h, w2T, b2, x2, out, ROWS, Dv, MLPv, 0);
}

// round 15
// speedup vs baseline: 2.8983x; 1.1648x over previous
#include <cuda_runtime.h>
#include <cuda_fp16.h>
#include <cstdint>

// Problem constants
#define Bv   8
#define Sv   1024
#define Dv   768
#define Hv   12
#define DHv  64
#define MLPv 3072
#define ROWS (Bv*Sv)            // 8192

// fp16 GEMM tiling
#define BKh      64                      // K halves per chunk
#define LDKh     72                      // 64 + 8 pad (144B row stride: ldmatrix conflict-free)
#define STAGE_H  (128*LDKh)              // halves per operand per stage
#define SMEMSZ   (6*STAGE_H*2)           // 3 stages x (A,B) halves = 110592 B

// fp16 attention tiling
#define KVPh 72                          // halves per row (144B, conflict-free)
#define PPh  72
#define ATTN_SMEM ((4*64*KVPh)*2 + 256*4)   // 37888 B

// ---------------- scratch (static device memory; no allocs) ----------------
__device__ __half g_xnh [ROWS*Dv];
__device__ __half g_qh  [ROWS*Dv];
__device__ __half g_kh  [ROWS*Dv];
__device__ __half g_vh  [ROWS*Dv];
__device__ __half g_ctxh[ROWS*Dv];
__device__ float  g_x2  [ROWS*Dv];
__device__ __half g_xn2h[ROWS*Dv];
__device__ __half g_h1h [ROWS*MLPv];
__device__ __half g_wqT[Dv*Dv];
__device__ __half g_wkT[Dv*Dv];
__device__ __half g_wvT[Dv*Dv];
__device__ __half g_woT[Dv*Dv];
__device__ __half g_w1T[MLPv*Dv];   // [3072, 768]
__device__ __half g_w2T[Dv*MLPv];   // [768, 3072]

// ---------------- helpers ----------------------------------------------------
__device__ __forceinline__ uint32_t smem_u32(const void* p) {
    uint32_t a;
    asm("{ .reg .u64 t; cvta.to.shared.u64 t, %1; cvt.u32.u64 %0, t; }" : "=r"(a) : "l"(p));
    return a;
}
__device__ __forceinline__ uint32_t h2_bits(__half2 h) {   // bitcast __half2 -> u32
    uint32_t u; *(__half2*)&u = h; return u;
}
__device__ __forceinline__ void mma_f16_16x8x16(float* d, const uint32_t* a, const uint32_t* b) {
    asm volatile(
        "mma.sync.aligned.m16n8k16.row.col.f32.f16.f16.f32 "
        "{%0,%1,%2,%3}, {%4,%5,%6,%7}, {%8,%9}, {%0,%1,%2,%3};"
        : "+f"(d[0]), "+f"(d[1]), "+f"(d[2]), "+f"(d[3])
        : "r"(a[0]), "r"(a[1]), "r"(a[2]), "r"(a[3]), "r"(b[0]), "r"(b[1]));
}
#define LDSM4(R, ADDR) \
    asm volatile("ldmatrix.sync.aligned.m8n8.x4.shared.b16 {%0,%1,%2,%3}, [%4];" \
        : "=r"((R)[0]), "=r"((R)[1]), "=r"((R)[2]), "=r"((R)[3]) : "r"(ADDR))
#define LDSM2(R, ADDR) \
    asm volatile("ldmatrix.sync.aligned.m8n8.x2.shared.b16 {%0,%1}, [%2];" \
        : "=r"((R)[0]), "=r"((R)[1]) : "r"(ADDR))
#define LDSM2T(R, ADDR) \
    asm volatile("ldmatrix.sync.aligned.m8n8.x2.trans.shared.b16 {%0,%1}, [%2];" \
        : "=r"((R)[0]), "=r"((R)[1]) : "r"(ADDR))

// ---------------- weight transposes (4x DxD fused) + fp16 --------------------
__global__ __launch_bounds__(256)
void transpose4_half(const float* __restrict__ W0, const float* __restrict__ W1,
                     const float* __restrict__ W2, const float* __restrict__ W3,
                     __half* __restrict__ T0, __half* __restrict__ T1,
                     __half* __restrict__ T2, __half* __restrict__ T3) {
    const float* W = (blockIdx.z == 0) ? W0 : (blockIdx.z == 1) ? W1 : (blockIdx.z == 2) ? W2 : W3;
    __half* T      = (blockIdx.z == 0) ? T0 : (blockIdx.z == 1) ? T1 : (blockIdx.z == 2) ? T2 : T3;
    __shared__ float t[32][33];
    int n0 = blockIdx.x * 32, k0 = blockIdx.y * 32;
    int tx = threadIdx.x & 31, ty = threadIdx.x >> 5;
    #pragma unroll
    for (int i = 0; i < 32; i += 8)
        t[ty + i][tx] = W[(size_t)(k0 + ty + i) * Dv + n0 + tx];
    __syncthreads();
    #pragma unroll
    for (int i = 0; i < 32; i += 8)
        T[(size_t)(n0 + ty + i) * Dv + k0 + tx] = __float2half_rn(t[tx][ty + i]);
}

// W [Kd, Nd] row-major  ->  WT [Nd, Kd] fp16 (for W1/W2)
__global__ __launch_bounds__(256)
void transpose_half(const float* __restrict__ W, __half* __restrict__ WT, int Kd, int Nd) {
    __shared__ float t[32][33];
    int n0 = blockIdx.x * 32, k0 = blockIdx.y * 32;
    int tx = threadIdx.x & 31, ty = threadIdx.x >> 5;
    #pragma unroll
    for (int i = 0; i < 32; i += 8)
        t[ty + i][tx] = W[(size_t)(k0 + ty + i) * Nd + n0 + tx];
    __syncthreads();
    #pragma unroll
    for (int i = 0; i < 32; i += 8)
        WT[(size_t)(n0 + ty + i) * Kd + k0 + tx] = __float2half_rn(t[tx][ty + i]);
}

// ---------------- LayerNorm -> fp16 output (GEMM A operand) ------------------
__global__ __launch_bounds__(256)
void ln_kernel(const float* __restrict__ x, const float* __restrict__ g,
               const float* __restrict__ b, __half* __restrict__ y) {
    int row = blockIdx.x;
    int t = threadIdx.x;
    const float* xr = x + (size_t)row * Dv;
    float v0 = xr[t], v1 = xr[t + 256], v2 = xr[t + 512];
    float s  = v0 + v1 + v2;
    float s2 = v0*v0 + v1*v1 + v2*v2;
    #pragma unroll
    for (int o = 16; o; o >>= 1) {
        s  += __shfl_xor_sync(0xFFFFFFFFu, s,  o);
        s2 += __shfl_xor_sync(0xFFFFFFFFu, s2, o);
    }
    __shared__ float rs[8], rs2[8];
    int w = t >> 5, lane = t & 31;
    if (lane == 0) { rs[w] = s; rs2[w] = s2; }
    __syncthreads();
    float tot = 0.f, tot2 = 0.f;
    #pragma unroll
    for (int i = 0; i < 8; i++) { tot += rs[i]; tot2 += rs2[i]; }
    float mu  = tot * (1.0f / Dv);
    float var = tot2 * (1.0f / Dv) - mu * mu;
    float inv = rsqrtf(var + 1e-6f);
    __half* yr = y + (size_t)row * Dv;
    yr[t]       = __float2half_rn((v0 - mu) * inv * g[t]       + b[t]);
    yr[t + 256] = __float2half_rn((v1 - mu) * inv * g[t + 256] + b[t + 256]);
    yr[t + 512] = __float2half_rn((v2 - mu) * inv * g[t + 512] + b[t + 512]);
}

// ---------------- fp16 tensor-core GEMM: C[M,N] = A[M,K] @ B[N,K]^T ----------
// EPI: 1 = +bias +res, fp32 out ; 2 = +bias, relu, fp16 out ;
//      3 = +bias, *scale, fp16 scatter [B,H,S,64]
template<int EPI>
__global__ __launch_bounds__(256, 2)
void hgemm(const __half* __restrict__ A, const __half* __restrict__ Bw,
           const float* __restrict__ bias, const float* __restrict__ res,
           void* __restrict__ Cout, int M, int N, int K, int mremap, float scale) {
    extern __shared__ __half hsm[];
    __half* sA = hsm;                        // [3][128][LDKh]
    __half* sB = hsm + 3 * STAGE_H;
    const uint32_t saA = smem_u32(sA);
    const uint32_t saB = smem_u32(sB);

    const int tid = threadIdx.x;
    int by = blockIdx.y;
    if (mremap) by = (by >> 2) * 8 + (by & 3);
    const int rowBase = by * 128, colBase = blockIdx.x * 128;
    const int warp = tid >> 5, lane = tid & 31;
    const int wm = warp >> 2, wn = warp & 3;     // warps: 2 (m) x 4 (n)

    auto load = [&](int j, int s) {
        int k0 = j * BKh;
        #pragma unroll
        for (int e = 0; e < 4; e++) {
            int idx = tid + 256 * e;             // 0..1023
            int row = idx >> 3, kc = (idx & 7) * 8;
            const __half* ga = A  + (size_t)(rowBase + row) * K + k0 + kc;
            const __half* gb = Bw + (size_t)(colBase + row) * K + k0 + kc;
            uint32_t da = saA + (uint32_t)(s * STAGE_H + row * LDKh + kc) * 2;
            uint32_t db = saB + (uint32_t)(s * STAGE_H + row * LDKh + kc) * 2;
            asm volatile("cp.async.cg.shared.global [%0], [%1], 16;" :: "r"(da), "l"(ga));
            asm volatile("cp.async.cg.shared.global [%0], [%1], 16;" :: "r"(db), "l"(gb));
        }
        asm volatile("cp.async.commit_group;" ::: "memory");
    };

    float acc[4][4][4];
    #pragma unroll
    for (int mt = 0; mt < 4; mt++)
        #pragma unroll
        for (int nt = 0; nt < 4; nt++)
            #pragma unroll
            for (int i = 0; i < 4; i++) acc[mt][nt][i] = 0.f;

    load(0, 0);
    load(1, 1);

    const int arow = lane & 15;
    const int acol = (lane < 16) ? 0 : 8;
    uint32_t aoff[4], boff[4];
    #pragma unroll
    for (int mt = 0; mt < 4; mt++)
        aoff[mt] = (uint32_t)((wm * 64 + mt * 16 + arow) * LDKh + acol) * 2;
    const int bl = lane & 15;
    #pragma unroll
    for (int nt = 0; nt < 4; nt++)
        boff[nt] = (uint32_t)((wn * 32 + nt * 8 + (bl & 7)) * LDKh + (bl >> 3) * 8) * 2;

    const int nch = K / BKh;
    for (int i = 0; i < nch; i++) {
        if (i + 2 < nch) load(i + 2, (i + 2) % 3);
        else asm volatile("cp.async.commit_group;" ::: "memory");
        asm volatile("cp.async.wait_group 2;" ::: "memory");
        __syncthreads();

        const uint32_t aS = saA + (uint32_t)((i % 3) * STAGE_H) * 2;
        const uint32_t bS = saB + (uint32_t)((i % 3) * STAGE_H) * 2;

        #pragma unroll
        for (int ks = 0; ks < 4; ks++) {
            uint32_t af[4][4], bf[4][2];
            #pragma unroll
            for (int mt = 0; mt < 4; mt++) LDSM4(af[mt], aS + aoff[mt] + ks * 32);
            #pragma unroll
            for (int nt = 0; nt < 4; nt++) LDSM2(bf[nt], bS + boff[nt] + ks * 32);
            #pragma unroll
            for (int mt = 0; mt < 4; mt++)
                #pragma unroll
                for (int nt = 0; nt < 4; nt++)
                    mma_f16_16x8x16(acc[mt][nt], af[mt], bf[nt]);
        }
        __syncthreads();
    }

    // Epilogue: regs -> smem tile -> coalesced stores
    float* tile = (float*)hsm;                // [128][132]
    const int r = lane >> 2, c = lane & 3;
    #pragma unroll
    for (int mt = 0; mt < 4; mt++)
        #pragma unroll
        for (int nt = 0; nt < 4; nt++) {
            int r0 = wm * 64 + mt * 16 + r;
            int c0 = wn * 32 + nt * 8 + 2 * c;
            tile[r0 * 132 + c0]           = acc[mt][nt][0];
            tile[r0 * 132 + c0 + 1]       = acc[mt][nt][1];
            tile[(r0 + 8) * 132 + c0]     = acc[mt][nt][2];
            tile[(r0 + 8) * 132 + c0 + 1] = acc[mt][nt][3];
        }
    __syncthreads();

    float4 b4 = *(const float4*)(bias + colBase + lane * 4);
    int col0 = colBase + lane * 4;
    int hh = col0 >> 6, dd = col0 & 63;          // for EPI==3
    #pragma unroll
    for (int rr = 0; rr < 16; rr++) {
        int trow = warp * 16 + rr;
        int row  = rowBase + trow;
        float4 v = *(float4*)&tile[trow * 132 + lane * 4];
        v.x += b4.x; v.y += b4.y; v.z += b4.z; v.w += b4.w;
        if (EPI == 1) {
            float4 r4 = *(const float4*)(res + (size_t)row * N + col0);
            v.x += r4.x; v.y += r4.y; v.z += r4.z; v.w += r4.w;
            *(float4*)&((float*)Cout)[(size_t)row * N + col0] = v;
        }
        if (EPI == 2) {
            __half2 h01 = __floats2half2_rn(fmaxf(v.x, 0.f), fmaxf(v.y, 0.f));
            __half2 h23 = __floats2half2_rn(fmaxf(v.z, 0.f), fmaxf(v.w, 0.f));
            *(uint2*)&((__half*)Cout)[(size_t)row * N + col0] = make_uint2(h2_bits(h01), h2_bits(h23));
        }
        if (EPI == 3) {
            __half2 h01 = __floats2half2_rn(v.x * scale, v.y * scale);
            __half2 h23 = __floats2half2_rn(v.z * scale, v.w * scale);
            int bb = row >> 10, ss = row & 1023;
            *(uint2*)&((__half*)Cout)[(((size_t)(bb * Hv + hh) * Sv + ss) * DHv) + dd] =
                make_uint2(h2_bits(h01), h2_bits(h23));
        }
    }
}

// ---------------- Attention (query rows < 512) via fp16 MMA flash -----------
// grid (8 qtiles, H, B), 256 threads = 8 warps = 4(m) x 2(n)
__global__ __launch_bounds__(256, 2)
void attn_fp16(const __half* __restrict__ Q, const __half* __restrict__ Kg,
               const __half* __restrict__ Vg, __half* __restrict__ ctx) {
    extern __shared__ __half hsm[];
    __half* Qs = hsm;                     // [64][KVPh]
    __half* Ks = Qs + 64 * KVPh;
    __half* Vs = Ks + 64 * KVPh;
    __half* Ps = Vs + 64 * KVPh;          // [64][PPh]
    float* redm = (float*)(Ps + 64 * PPh);  // [2][64]
    float* redl = redm + 128;               // [2][64]

    const int b = blockIdx.z, h = blockIdx.y;
    const int bh = b * Hv + h;
    const int qbase = blockIdx.x * 64;
    const int tid = threadIdx.x, warp = tid >> 5, lane = tid & 31;
    const int wm = warp >> 1, wn = warp & 1;
    const int r = lane >> 2, c = lane & 3;
    const int m0 = wm * 16;
    const int arow = lane & 15;
    const int acol = (lane < 16) ? 0 : 8;
    const int bl = lane & 15;

    const uint32_t sq = smem_u32(Qs), sk = smem_u32(Ks), sv = smem_u32(Vs), sp = smem_u32(Ps);

    // Stage Q (already scaled by 0.125 in QKV epilogue)
    const __half* Qbh = Q + ((size_t)bh * Sv + qbase) * DHv;
    #pragma unroll
    for (int e = 0; e < 2; e++) {
        int idx = tid + e * 256;                 // 0..511
        int row = idx >> 3, kc = (idx & 7) * 8;
        asm volatile("cp.async.cg.shared.global [%0], [%1], 16;"
                     :: "r"(sq + (uint32_t)(row * KVPh + kc) * 2), "l"(Qbh + row * DHv + kc));
    }
    asm volatile("cp.async.commit_group;" ::: "memory");
    asm volatile("cp.async.wait_group 0;" ::: "memory");
    __syncthreads();

    // Preload Q fragments (A operand): 4 k16 steps over DH=64
    uint32_t qf[4][4];
    #pragma unroll
    for (int ks = 0; ks < 4; ks++)
        LDSM4(qf[ks], sq + (uint32_t)((m0 + arow) * KVPh + acol + ks * 16) * 2);

    float accO[4][4];
    #pragma unroll
    for (int nt = 0; nt < 4; nt++)
        #pragma unroll
        for (int i = 0; i < 4; i++) accO[nt][i] = 0.f;
    float mrow0 = -1e30f, mrow1 = -1e30f, lrow0 = 0.f, lrow1 = 0.f;

    const __half* Kbh = Kg + (size_t)bh * Sv * DHv;
    const __half* Vbh = Vg + (size_t)bh * Sv * DHv;

    for (int kt = 0; kt < Sv; kt += 64) {
        __syncthreads();
        #pragma unroll
        for (int e = 0; e < 2; e++) {
            int idx = tid + e * 256;
            int row = idx >> 3, kc = (idx & 7) * 8;
            uint32_t off = (uint32_t)(row * KVPh + kc) * 2;
            asm volatile("cp.async.cg.shared.global [%0], [%1], 16;"
                         :: "r"(sk + off), "l"(Kbh + (size_t)(kt + row) * DHv + kc));
            asm volatile("cp.async.cg.shared.global [%0], [%1], 16;"
                         :: "r"(sv + off), "l"(Vbh + (size_t)(kt + row) * DHv + kc));
        }
        asm volatile("cp.async.commit_group;" ::: "memory");
        asm volatile("cp.async.wait_group 0;" ::: "memory");
        __syncthreads();

        // S = Q @ K^T : warp rows m0..+15, keys wn*32..+31 (4 n-tiles of 8)
        float sacc[4][4];
        #pragma unroll
        for (int nt = 0; nt < 4; nt++)
            #pragma unroll
            for (int i = 0; i < 4; i++) sacc[nt][i] = 0.f;
        #pragma unroll
        for (int ks = 0; ks < 4; ks++) {
            uint32_t bf[4][2];
            #pragma unroll
            for (int nt = 0; nt < 4; nt++)
                LDSM2(bf[nt], sk + (uint32_t)((wn * 32 + nt * 8 + (bl & 7)) * KVPh + (bl >> 3) * 8 + ks * 16) * 2);
            #pragma unroll
            for (int nt = 0; nt < 4; nt++)
                mma_f16_16x8x16(sacc[nt], qf[ks], bf[nt]);
        }

        // Row max
        float mx0 = sacc[0][0], mx1 = sacc[0][2];
        #pragma unroll
        for (int nt = 0; nt < 4; nt++) {
            mx0 = fmaxf(mx0, fmaxf(sacc[nt][0], sacc[nt][1]));
            mx1 = fmaxf(mx1, fmaxf(sacc[nt][2], sacc[nt][3]));
        }
        mx0 = fmaxf(mx0, __shfl_xor_sync(0xFFFFFFFFu, mx0, 1));
        mx0 = fmaxf(mx0, __shfl_xor_sync(0xFFFFFFFFu, mx0, 2));
        mx1 = fmaxf(mx1, __shfl_xor_sync(0xFFFFFFFFu, mx1, 1));
        mx1 = fmaxf(mx1, __shfl_xor_sync(0xFFFFFFFFu, mx1, 2));
        if (c == 0) {
            redm[wn * 64 + m0 + r]     = mx0;
            redm[wn * 64 + m0 + r + 8] = mx1;
        }
        __syncthreads();
        float mn0 = fmaxf(mrow0, fmaxf(redm[m0 + r],     redm[64 + m0 + r]));
        float mn1 = fmaxf(mrow1, fmaxf(redm[m0 + r + 8], redm[64 + m0 + r + 8]));

        // exp, store P (fp16), partial row sums
        float sum0 = 0.f, sum1 = 0.f;
        #pragma unroll
        for (int nt = 0; nt < 4; nt++) {
            float p00 = __expf(sacc[nt][0] - mn0);
            float p01 = __expf(sacc[nt][1] - mn0);
            float p10 = __expf(sacc[nt][2] - mn1);
            float p11 = __expf(sacc[nt][3] - mn1);
            sum0 += p00 + p01;
            sum1 += p10 + p11;
            int col = wn * 32 + nt * 8 + 2 * c;
            *(__half2*)&Ps[(m0 + r) * PPh + col]     = __floats2half2_rn(p00, p01);
            *(__half2*)&Ps[(m0 + r + 8) * PPh + col] = __floats2half2_rn(p10, p11);
        }
        sum0 += __shfl_xor_sync(0xFFFFFFFFu, sum0, 1);
        sum0 += __shfl_xor_sync(0xFFFFFFFFu, sum0, 2);
        sum1 += __shfl_xor_sync(0xFFFFFFFFu, sum1, 1);
        sum1 += __shfl_xor_sync(0xFFFFFFFFu, sum1, 2);
        if (c == 0) {
            redl[wn * 64 + m0 + r]     = sum0;
            redl[wn * 64 + m0 + r + 8] = sum1;
        }
        float cor0 = __expf(mrow0 - mn0), cor1 = __expf(mrow1 - mn1);
        mrow0 = mn0; mrow1 = mn1;
        #pragma unroll
        for (int nt = 0; nt < 4; nt++) {
            accO[nt][0] *= cor0; accO[nt][1] *= cor0;
            accO[nt][2] *= cor1; accO[nt][3] *= cor1;
        }
        __syncthreads();
        lrow0 = lrow0 * cor0 + redl[m0 + r]     + redl[64 + m0 + r];
        lrow1 = lrow1 * cor1 + redl[m0 + r + 8] + redl[64 + m0 + r + 8];

        // O += P @ V : A = P[m][kv] (ldmatrix), B = V^T via ldmatrix.trans
        #pragma unroll
        for (int ks = 0; ks < 4; ks++) {
            uint32_t pf[4];
            LDSM4(pf, sp + (uint32_t)((m0 + arow) * PPh + acol + ks * 16) * 2);
            uint32_t vb[4][2];
            #pragma unroll
            for (int nt = 0; nt < 4; nt++)
                LDSM2T(vb[nt], sv + (uint32_t)((ks * 16 + bl) * KVPh + wn * 32 + nt * 8) * 2);
            #pragma unroll
            for (int nt = 0; nt < 4; nt++)
                mma_f16_16x8x16(accO[nt], pf, vb[nt]);
        }
    }

    float il0 = 1.0f / lrow0, il1 = 1.0f / lrow1;
    #pragma unroll
    for (int nt = 0; nt < 4; nt++) {
        int d0 = wn * 32 + nt * 8 + 2 * c;
        int row0 = qbase + m0 + r, row1 = row0 + 8;
        size_t a0 = ((size_t)b * Sv + row0) * Dv + h * DHv + d0;
        size_t a1 = ((size_t)b * Sv + row1) * Dv + h * DHv + d0;
        *(__half2*)&ctx[a0] = __floats2half2_rn(accO[nt][0] * il0, accO[nt][1] * il0);
        *(__half2*)&ctx[a1] = __floats2half2_rn(accO[nt][2] * il1, accO[nt][3] * il1);
    }
}

// ---------------- Masked rows (>=512): ctx = mean_k v -----------------------
__global__ __launch_bounds__(256)
void meanv_kernel(const __half* __restrict__ Vg, __half* __restrict__ ctx) {
    const int h = blockIdx.x, b = blockIdx.y;
    const int bh = b * Hv + h;
    const int tid = threadIdx.x;
    const int d = tid & 63, slice = tid >> 6;
    const __half* Vbh = Vg + (size_t)bh * Sv * DHv;
    float s = 0.f;
    for (int k = slice * 256; k < slice * 256 + 256; k++)
        s += __half2float(Vbh[k * DHv + d]);
    __shared__ float red[4][64];
    __shared__ __half mv[64];
    red[slice][d] = s;
    __syncthreads();
    if (tid < 64)
        mv[tid] = __float2half_rn((red[0][tid] + red[1][tid] + red[2][tid] + red[3][tid]) * (1.0f / Sv));
    __syncthreads();
    __half val = mv[d];
    for (int r = slice; r < 512; r += 4)
        ctx[((size_t)b * Sv + 512 + r) * Dv + h * DHv + d] = val;
}

// ---------------- driver -----------------------------------------------------
extern "C" void kernel_launch(void* const* d_in, const int* in_sizes, int n_in,
                              void* d_out, int out_size) {
    const float* x    = (const float*)d_in[0];
    const float* Wq   = (const float*)d_in[1];
    const float* bq   = (const float*)d_in[2];
    const float* Wk   = (const float*)d_in[3];
    const float* bk   = (const float*)d_in[4];
    const float* Wv   = (const float*)d_in[5];
    const float* bv   = (const float*)d_in[6];
    const float* Wo   = (const float*)d_in[7];
    const float* bo   = (const float*)d_in[8];
    const float* ln1g = (const float*)d_in[9];
    const float* ln1b = (const float*)d_in[10];
    const float* ln2g = (const float*)d_in[11];
    const float* ln2b = (const float*)d_in[12];
    const float* W1   = (const float*)d_in[13];
    const float* b1   = (const float*)d_in[14];
    const float* W2   = (const float*)d_in[15];
    const float* b2   = (const float*)d_in[16];
    float* out = (float*)d_out;

    __half *xnh, *qh, *kh, *vh, *ctxh, *xn2h, *h1h, *wqT, *wkT, *wvT, *woT, *w1T, *w2T;
    float *x2;
    cudaGetSymbolAddress((void**)&xnh,  g_xnh);
    cudaGetSymbolAddress((void**)&qh,   g_qh);
    cudaGetSymbolAddress((void**)&kh,   g_kh);
    cudaGetSymbolAddress((void**)&vh,   g_vh);
    cudaGetSymbolAddress((void**)&ctxh, g_ctxh);
    cudaGetSymbolAddress((void**)&x2,   g_x2);
    cudaGetSymbolAddress((void**)&xn2h, g_xn2h);
    cudaGetSymbolAddress((void**)&h1h,  g_h1h);
    cudaGetSymbolAddress((void**)&wqT,  g_wqT);
    cudaGetSymbolAddress((void**)&wkT,  g_wkT);
    cudaGetSymbolAddress((void**)&wvT,  g_wvT);
    cudaGetSymbolAddress((void**)&woT,  g_woT);
    cudaGetSymbolAddress((void**)&w1T,  g_w1T);
    cudaGetSymbolAddress((void**)&w2T,  g_w2T);

    cudaFuncSetAttribute(hgemm<1>, cudaFuncAttributeMaxDynamicSharedMemorySize, SMEMSZ);
    cudaFuncSetAttribute(hgemm<2>, cudaFuncAttributeMaxDynamicSharedMemorySize, SMEMSZ);
    cudaFuncSetAttribute(hgemm<3>, cudaFuncAttributeMaxDynamicSharedMemorySize, SMEMSZ);
    cudaFuncSetAttribute(attn_fp16, cudaFuncAttributeMaxDynamicSharedMemorySize, ATTN_SMEM);

    // Weight transposes (fp16): 4 DxD fused + W1 + W2
    transpose4_half<<<dim3(Dv/32, Dv/32, 4), 256>>>(Wq, Wk, Wv, Wo, wqT, wkT, wvT, woT);
    transpose_half<<<dim3(MLPv/32, Dv/32),   256>>>(W1, w1T, Dv,   MLPv);
    transpose_half<<<dim3(Dv/32,   MLPv/32), 256>>>(W2, w2T, MLPv, Dv);

    // 1. LN1 -> fp16
    ln_kernel<<<ROWS, 256>>>(x, ln1g, ln1b, xnh);

    // 2. QKV projections (fp16 MMA -> fp16 scatter [B,H,S,64]; Q pre-scaled 0.125)
    dim3 gD(Dv/128, ROWS/128);             // (6, 64)
    dim3 gQ(Dv/128, ROWS/256);             // (6, 32) remapped: rows<512 per batch
    hgemm<3><<<gQ, 256, SMEMSZ>>>(xnh, wqT, bq, nullptr, qh, ROWS, Dv, Dv, 1, 0.125f);
    hgemm<3><<<gD, 256, SMEMSZ>>>(xnh, wkT, bk, nullptr, kh, ROWS, Dv, Dv, 0, 1.0f);
    hgemm<3><<<gD, 256, SMEMSZ>>>(xnh, wvT, bv, nullptr, vh, ROWS, Dv, Dv, 0, 1.0f);

    // 3. Attention (fp16 MMA flash) + masked-row mean -> ctx fp16
    attn_fp16<<<dim3(8, Hv, Bv), 256, ATTN_SMEM>>>(qh, kh, vh, ctxh);
    meanv_kernel<<<dim3(Hv, Bv), 256>>>(vh, ctxh);

    // 4. Output projection + residual (fp32 out)
    hgemm<1><<<gD, 256, SMEMSZ>>>(ctxh, woT, bo, x, x2, ROWS, Dv, Dv, 0, 1.0f);

    // 5. LN2 -> fp16
    ln_kernel<<<ROWS, 256>>>(x2, ln2g, ln2b, xn2h);

    // 6. MLP
    dim3 gM(MLPv/128, ROWS/128);           // (24, 64)
    hgemm<2><<<gM, 256, SMEMSZ>>>(xn2h, w1T, b1, nullptr, h1h, ROWS, MLPv, Dv, 0, 1.0f);
    hgemm<1><<<gD, 256, SMEMSZ>>>(h1h, w2T, b2, x2, out, ROWS, Dv, MLPv, 0, 1.0f);
}